// round 13
// baseline (speedup 1.0000x reference)
#include <cuda_runtime.h>
#include <cstdint>

#define B_  256
#define N_  4096
#define M_  64
#define C_  512
#define EPSV 1e-8f
#define NPASSBLK 296
#define NPBE 444
#define NPAIRS   4096
#define RBN ((size_t)B_ * N_)
#define PEN 874
#define PE1 490
#define PEB ((size_t)B_ * PEN)
#define GTB ((size_t)B_ * 2048)
#define OTB ((size_t)B_ * 64)

// ---------------- packed f32x2 helpers (sm_103a FFMA2) ----------------
struct px2 { unsigned long long u; };
__device__ __forceinline__ px2 pk(float x, float y) {
    px2 r; asm("mov.b64 %0,{%1,%2};" : "=l"(r.u) : "f"(x), "f"(y)); return r;
}
__device__ __forceinline__ float2 up(px2 a) {
    float2 f; asm("mov.b64 {%0,%1},%2;" : "=f"(f.x), "=f"(f.y) : "l"(a.u)); return f;
}
__device__ __forceinline__ px2 fma2(px2 a, px2 b, px2 c) {
    px2 r; asm("fma.rn.f32x2 %0,%1,%2,%3;" : "=l"(r.u) : "l"(a.u), "l"(b.u), "l"(c.u)); return r;
}

// ---------------- device scratch ----------------
__device__ __align__(16) float g_mem[(size_t)B_ * N_ * M_];      // v2 working memory (written once, pass C)
__device__ __align__(16) float g_x[B_ * 320];
__device__ __align__(16) float g_gates4[4 * GTB];
__device__ __align__(16) float g_c[B_ * C_];
__device__ __align__(16) float g_h[B_ * C_];
__device__ __align__(16) float g_pe8[8 * PEB];
__device__ __align__(16) float g_out4[4 * OTB];
__device__ __align__(16) float g_k[7 * B_ * M_];
__device__ float g_knorm[7 * B_];
__device__ float g_beta[7 * B_];
__device__ float g_gate[7 * B_];
__device__ float g_s[7 * B_ * 3];
__device__ float g_gamma[7 * B_];
__device__ __align__(16) float g_e[3 * B_ * M_];
__device__ __align__(16) float g_a[3 * B_ * M_];
__device__ __align__(16) float g_red[11 * RBN];                  // reduction slots
__device__ __align__(16) float g_w[7 * RBN];                     // per-head weights, slot = head index
__device__ __align__(16) float g_rpart[5 * B_ * 16 * M_];        // colsum partials: reads0,2,4, Sa, Sb
__device__ float g_ak[B_];    // a5 . k6
__device__ float g_aa[B_];    // |a5|^2
__device__ float g_A2[B_];    // a1 . k2
__device__ float g_A3[B_];    // a1 . k3
__device__ float g_Aaa[B_];   // |a1|^2
__device__ float g_T[B_];     // sum_n w6 w5
__device__ __align__(16) float g_state[B_ * 768];

#define RED(i) (g_red + (size_t)(i) * RBN)

// ---------------- helpers ----------------
__device__ __forceinline__ float sigf(float x) { return 1.f / (1.f + expf(-x)); }
__device__ __forceinline__ float softplusf(float x) { return x > 20.f ? x : log1pf(expf(x)); }

// ---------------- build x = [in_data | prev_reads 0..3] ----------------
__global__ void build_x_kernel(const float* __restrict__ in_data,
                               const float* __restrict__ prev_reads) {
    int idx = blockIdx.x * blockDim.x + threadIdx.x;
    if (idx >= B_ * 320) return;
    int b = idx / 320, j = idx % 320;
    float v;
    if (j < 64) v = in_data[b * 64 + j];
    else { int i = (j - 64) >> 6, m = (j - 64) & 63; v = prev_reads[((size_t)i * B_ + b) * 64 + m]; }
    g_x[idx] = v;
}

// gates GEMM, 64x64 tile / 4x4 microtile, split-K 4: partials -> g_gates4[z]
__global__ void gates_gemm_kernel(const float* __restrict__ h0,
                                  const float* __restrict__ Wih,
                                  const float* __restrict__ Whh) {
    __shared__ __align__(16) float As[16][64];
    __shared__ __align__(16) float Bs[16][64];
    int tid = threadIdx.x;
    int z = blockIdx.z;
    const float* A = (z < 2) ? g_x : h0;
    const float* Bw = (z < 2) ? Wih : Whh;
    int K = (z < 2) ? 320 : 512;
    int kbeg = (z == 0) ? 0 : (z == 1) ? 160 : (z == 2) ? 0 : 256;
    int kend = (z == 0) ? 160 : (z == 1) ? 320 : (z == 2) ? 256 : 512;
    int m0 = blockIdx.y * 64, n0 = blockIdx.x * 64;
    int l_r = tid >> 2, l_k = (tid & 3) * 4;
    int ty = tid >> 4, tx = tid & 15;
    float acc[4][4] = {};
    const float* ap = A + (size_t)(m0 + l_r) * K + l_k;
    const float* bp = Bw + (size_t)(n0 + l_r) * K + l_k;
    float4 av = *(const float4*)(ap + kbeg);
    float4 bv = *(const float4*)(bp + kbeg);
    for (int k0 = kbeg; k0 < kend; k0 += 16) {
        __syncthreads();
        As[l_k + 0][l_r] = av.x; As[l_k + 1][l_r] = av.y;
        As[l_k + 2][l_r] = av.z; As[l_k + 3][l_r] = av.w;
        Bs[l_k + 0][l_r] = bv.x; Bs[l_k + 1][l_r] = bv.y;
        Bs[l_k + 2][l_r] = bv.z; Bs[l_k + 3][l_r] = bv.w;
        if (k0 + 16 < kend) {
            av = *(const float4*)(ap + k0 + 16);
            bv = *(const float4*)(bp + k0 + 16);
        }
        __syncthreads();
#pragma unroll
        for (int kk = 0; kk < 16; kk++) {
            float4 a = *(const float4*)&As[kk][ty << 2];
            float4 b = *(const float4*)&Bs[kk][tx << 2];
            acc[0][0] += a.x * b.x; acc[0][1] += a.x * b.y; acc[0][2] += a.x * b.z; acc[0][3] += a.x * b.w;
            acc[1][0] += a.y * b.x; acc[1][1] += a.y * b.y; acc[1][2] += a.y * b.z; acc[1][3] += a.y * b.w;
            acc[2][0] += a.z * b.x; acc[2][1] += a.z * b.y; acc[2][2] += a.z * b.z; acc[2][3] += a.z * b.w;
            acc[3][0] += a.w * b.x; acc[3][1] += a.w * b.y; acc[3][2] += a.w * b.z; acc[3][3] += a.w * b.w;
        }
    }
    float* outp = g_gates4 + (size_t)z * GTB;
#pragma unroll
    for (int i = 0; i < 4; i++) {
        int m = m0 + (ty << 2) + i;
#pragma unroll
        for (int j = 0; j < 4; j++) {
            int n = n0 + (tx << 2) + j;
            outp[(size_t)m * 2048 + n] = acc[i][j];
        }
    }
}

// head-param GEMM, trimmed N=874, 64x64 tile / 4x4 microtile, split-K 8 x 64
__global__ void headpe_gemm_kernel(const float* __restrict__ Wa,
                                   const float* __restrict__ We) {
    __shared__ __align__(16) float As[16][64];
    __shared__ __align__(16) float Bs[16][64];
    const int K = 512;
    int tid = threadIdx.x;
    int z = blockIdx.z;
    int kbeg = z * 64, kend = kbeg + 64;
    int m0 = blockIdx.y * 64, n0 = blockIdx.x * 64;
    int l_r = tid >> 2, l_k = (tid & 3) * 4;
    int ty = tid >> 4, tx = tid & 15;
    int brow = n0 + l_r;
    const float* browp = (brow < PE1) ? (Wa + (size_t)brow * K)
                                      : (We + (size_t)(brow - PE1) * K);
    bool bok = (brow < PEN);
    const float* ap = g_c + (size_t)(m0 + l_r) * K + l_k;
    float4 av = *(const float4*)(ap + kbeg);
    float4 bv = bok ? *(const float4*)(browp + l_k + kbeg) : make_float4(0.f, 0.f, 0.f, 0.f);
    float acc[4][4] = {};
    for (int k0 = kbeg; k0 < kend; k0 += 16) {
        __syncthreads();
        As[l_k + 0][l_r] = av.x; As[l_k + 1][l_r] = av.y;
        As[l_k + 2][l_r] = av.z; As[l_k + 3][l_r] = av.w;
        Bs[l_k + 0][l_r] = bv.x; Bs[l_k + 1][l_r] = bv.y;
        Bs[l_k + 2][l_r] = bv.z; Bs[l_k + 3][l_r] = bv.w;
        if (k0 + 16 < kend) {
            av = *(const float4*)(ap + k0 + 16);
            bv = bok ? *(const float4*)(browp + l_k + k0 + 16) : make_float4(0.f, 0.f, 0.f, 0.f);
        }
        __syncthreads();
#pragma unroll
        for (int kk = 0; kk < 16; kk++) {
            float4 a = *(const float4*)&As[kk][ty << 2];
            float4 b = *(const float4*)&Bs[kk][tx << 2];
            acc[0][0] += a.x * b.x; acc[0][1] += a.x * b.y; acc[0][2] += a.x * b.z; acc[0][3] += a.x * b.w;
            acc[1][0] += a.y * b.x; acc[1][1] += a.y * b.y; acc[1][2] += a.y * b.z; acc[1][3] += a.y * b.w;
            acc[2][0] += a.z * b.x; acc[2][1] += a.z * b.y; acc[2][2] += a.z * b.z; acc[2][3] += a.z * b.w;
            acc[3][0] += a.w * b.x; acc[3][1] += a.w * b.y; acc[3][2] += a.w * b.z; acc[3][3] += a.w * b.w;
        }
    }
    float* outp = g_pe8 + (size_t)z * PEB;
#pragma unroll
    for (int i = 0; i < 4; i++) {
        int m = m0 + (ty << 2) + i;
#pragma unroll
        for (int j = 0; j < 4; j++) {
            int n = n0 + (tx << 2) + j;
            if (n < PEN) outp[(size_t)m * PEN + n] = acc[i][j];
        }
    }
}

// output GEMM, split-K 4 x 192: partials -> g_out4[z]   (N=64, K=768)
__global__ void out_gemm_kernel(const float* __restrict__ Wo) {
    __shared__ __align__(16) float As[16][32];
    __shared__ __align__(16) float Bs[16][64];
    const int NN = 64, K = 768;
    int tid = threadIdx.x;
    int z = blockIdx.z;
    int kbeg = z * 192, kend = kbeg + 192;
    int m0 = blockIdx.y * 32, n0 = 0;
    int la_r = tid >> 3, la_k = (tid & 7) * 2;
    int lb_r = tid >> 2, lb_k = (tid & 3) * 4;
    int ty = tid >> 4, tx = tid & 15;
    const float* ap = g_state + (size_t)(m0 + la_r) * K + la_k;
    const float* bp = Wo + (size_t)(n0 + lb_r) * K + lb_k;
    float2 av = *(const float2*)(ap + kbeg);
    float4 bv = *(const float4*)(bp + kbeg);
    float acc[2][4] = {};
    for (int k0 = kbeg; k0 < kend; k0 += 16) {
        __syncthreads();
        As[la_k][la_r] = av.x; As[la_k + 1][la_r] = av.y;
        Bs[lb_k + 0][lb_r] = bv.x; Bs[lb_k + 1][lb_r] = bv.y;
        Bs[lb_k + 2][lb_r] = bv.z; Bs[lb_k + 3][lb_r] = bv.w;
        if (k0 + 16 < kend) {
            av = *(const float2*)(ap + k0 + 16);
            bv = *(const float4*)(bp + k0 + 16);
        }
        __syncthreads();
#pragma unroll
        for (int kk = 0; kk < 16; kk++) {
            float2 a = *(const float2*)&As[kk][ty << 1];
            float4 b = *(const float4*)&Bs[kk][tx << 2];
            acc[0][0] += a.x * b.x; acc[0][1] += a.x * b.y; acc[0][2] += a.x * b.z; acc[0][3] += a.x * b.w;
            acc[1][0] += a.y * b.x; acc[1][1] += a.y * b.y; acc[1][2] += a.y * b.z; acc[1][3] += a.y * b.w;
        }
    }
    float* outp = g_out4 + (size_t)z * OTB;
#pragma unroll
    for (int i = 0; i < 2; i++) {
        int m = m0 + (ty << 1) + i;
#pragma unroll
        for (int j = 0; j < 4; j++) {
            int n = n0 + (tx << 2) + j;
            outp[(size_t)m * NN + n] = acc[i][j];
        }
    }
}

// out finalize: sum split-K partials + bias, sigmoid
__global__ void out_fin_kernel(const float* __restrict__ bo, float* __restrict__ C) {
    int idx = blockIdx.x * 256 + threadIdx.x;
    if (idx >= B_ * 64) return;
    int n = idx & 63;
    float s = g_out4[idx] + g_out4[OTB + idx] + g_out4[2 * OTB + idx] + g_out4[3 * OTB + idx];
    C[idx] = sigf(s + bo[n]);
}

// ---------------- LSTM pointwise (sums gates split-K partials + biases) ----------------
__global__ void lstm_kernel(const float* __restrict__ c0,
                            const float* __restrict__ bih, const float* __restrict__ bhh) {
    int idx = blockIdx.x * blockDim.x + threadIdx.x;
    if (idx >= B_ * C_) return;
    int b = idx / C_, j = idx % C_;
    size_t base = (size_t)b * 2048;
    float g4[4];
#pragma unroll
    for (int gi = 0; gi < 4; ++gi) {
        size_t o = base + gi * 512 + j;
        g4[gi] = g_gates4[o] + g_gates4[GTB + o] + g_gates4[2 * GTB + o] + g_gates4[3 * GTB + o]
               + bih[gi * 512 + j] + bhh[gi * 512 + j];
    }
    float c = sigf(g4[1]) * c0[idx] + sigf(g4[0]) * tanhf(g4[2]);
    g_c[idx] = c;
    g_h[idx] = sigf(g4[3]) * tanhf(c);
}

// ---------------- head activations ----------------
// trimmed layout: [0,490): addr heads 0..6 (70 each); [490,874): ea heads 0..2 (128 each)
__global__ void head_act_kernel(const float* __restrict__ ba, const float* __restrict__ be) {
    __shared__ float spe[PEN];
    int b = blockIdx.x;
    int tid = threadIdx.x;
    for (int j = tid; j < PEN; j += 256) {
        size_t o = (size_t)b * PEN + j;
        float bias = (j < PE1) ? ba[j] : be[j - PE1];
        float s = 0.f;
#pragma unroll
        for (int zz = 0; zz < 8; ++zz) s += g_pe8[(size_t)zz * PEB + o];
        spe[j] = s + bias;
    }
    __syncthreads();
    int wid = tid >> 5, lane = tid & 31;
    if (wid < 7) {
        int hd = wid;
        const float* p = spe + hd * 70;
        float ssq = 0.f;
        for (int j = lane; j < 64; j += 32) {
            float kv = tanhf(p[j]);
            g_k[((size_t)hd * B_ + b) * 64 + j] = kv;
            ssq += kv * kv;
        }
#pragma unroll
        for (int o = 16; o; o >>= 1) ssq += __shfl_xor_sync(0xffffffffu, ssq, o);
        if (lane == 0) {
            int hb = hd * B_ + b;
            g_knorm[hb] = sqrtf(ssq);
            g_beta[hb] = softplusf(p[64]);
            g_gate[hb] = sigf(p[65]);
            float s0 = p[66], s1 = p[67], s2 = p[68];
            float mx = fmaxf(s0, fmaxf(s1, s2));
            float e0 = expf(s0 - mx), e1 = expf(s1 - mx), e2 = expf(s2 - mx);
            float inv = 1.f / (e0 + e1 + e2);
            g_s[hb * 3 + 0] = e0 * inv; g_s[hb * 3 + 1] = e1 * inv; g_s[hb * 3 + 2] = e2 * inv;
            g_gamma[hb] = 1.f + softplusf(p[69]);
        }
    } else {
        for (int wh = 0; wh < 3; ++wh) {
            const float* ea = spe + PE1 + wh * 128;
            for (int j = lane; j < 64; j += 32) {
                g_e[((size_t)wh * B_ + b) * 64 + j] = sigf(ea[j]);
                g_a[((size_t)wh * B_ + b) * 64 + j] = tanhf(ea[64 + j]);
            }
        }
        const float* ea2 = spe + PE1 + 2 * 128;
        const float* ea0 = spe + PE1 + 0 * 128;
        const float* p6  = spe + 6 * 70;
        const float* p2  = spe + 2 * 70;
        const float* p3  = spe + 3 * 70;
        float pak = 0.f, paa = 0.f, pa2 = 0.f, pa3 = 0.f, p11 = 0.f;
        for (int j = lane; j < 64; j += 32) {
            float a5v = tanhf(ea2[64 + j]);
            float k6v = tanhf(p6[j]);
            float a1v = tanhf(ea0[64 + j]);
            float k2v = tanhf(p2[j]);
            float k3v = tanhf(p3[j]);
            pak += a5v * k6v; paa += a5v * a5v;
            pa2 += a1v * k2v; pa3 += a1v * k3v; p11 += a1v * a1v;
        }
#pragma unroll
        for (int o = 16; o; o >>= 1) {
            pak += __shfl_xor_sync(0xffffffffu, pak, o);
            paa += __shfl_xor_sync(0xffffffffu, paa, o);
            pa2 += __shfl_xor_sync(0xffffffffu, pa2, o);
            pa3 += __shfl_xor_sync(0xffffffffu, pa3, o);
            p11 += __shfl_xor_sync(0xffffffffu, p11, o);
        }
        if (lane == 0) {
            g_ak[b] = pak; g_aa[b] = paa;
            g_A2[b] = pa2; g_A3[b] = pa3; g_Aaa[b] = p11;
        }
    }
}

// =================== persistent grid-stride memory passes ===================
#define PASS_HEAD(NB)                                                       \
    int tid = threadIdx.x, lane = tid & 31, warp = tid >> 5;                \
    int c = lane & 7, rg = lane >> 3, col0 = c * 8;                         \
    int p0 = (NPAIRS * blockIdx.x) / (NB);                                  \
    int p1 = (NPAIRS * (blockIdx.x + 1)) / (NB);                            \
    int Lend = p1 * 8;

#define LOADOP(dst, baseptr) {                                              \
    const float4* _q = (const float4*)((baseptr) + col0);                   \
    float4 _u0 = __ldg(_q), _u1 = __ldg(_q + 1);                            \
    dst[0] = pk(_u0.x, _u0.y); dst[1] = pk(_u0.z, _u0.w);                   \
    dst[2] = pk(_u1.x, _u1.y); dst[3] = pk(_u1.z, _u1.w); }
#define LOADOPN(dst, baseptr) {                                             \
    const float4* _q = (const float4*)((baseptr) + col0);                   \
    float4 _u0 = __ldg(_q), _u1 = __ldg(_q + 1);                            \
    dst[0] = pk(-_u0.x, -_u0.y); dst[1] = pk(-_u0.z, -_u0.w);               \
    dst[2] = pk(-_u1.x, -_u1.y); dst[3] = pk(-_u1.z, -_u1.w); }

__device__ __forceinline__ void reads_epilogue(px2* acc, float (*sred)[64],
                                               int lane, int warp, int c, int tid,
                                               int pair, int slot) {
    float va[8];
#pragma unroll
    for (int i = 0; i < 4; ++i) { float2 f = up(acc[i]); va[2 * i] = f.x; va[2 * i + 1] = f.y; }
#pragma unroll
    for (int t = 0; t < 8; ++t) {
        va[t] += __shfl_xor_sync(0xffffffffu, va[t], 8);
        va[t] += __shfl_xor_sync(0xffffffffu, va[t], 16);
    }
    if (lane < 8) {
#pragma unroll
        for (int t = 0; t < 8; ++t) sred[warp][c * 8 + t] = va[t];
    }
    __syncthreads();
    if (tid < 64) {
        float s = 0.f;
#pragma unroll
        for (int wv = 0; wv < 8; ++wv) s += sred[wv][tid];
        g_rpart[(size_t)slot * B_ * 16 * 64 + (size_t)pair * 64 + tid] = s;
    }
    __syncthreads();
}

// ---- Pass A: 11 reductions on mem0 (heads 0-3 material), reduce-scatter ----
// slots: 0:dot0 1:dot1 2:nrm0 3:u2a 4:u2b 5:u3a 6:u3b 7:v1a 8:v2a 9:v3a 10:v4a
__global__ __launch_bounds__(256, 2) void passA_kernel(const float* __restrict__ mem0) {
    PASS_HEAD(NPASSBLK);
    float4 bufA[4], bufB[4];
#define LD_A(L) { size_t n = (size_t)(L) * 32 + warp * 4 + rg;              \
        const float4* p = (const float4*)(mem0 + n * 64 + col0);            \
        bufA[(L) & 3] = __ldcs(p); bufB[(L) & 3] = __ldcs(p + 1); }
    LD_A(p0 * 8); LD_A(p0 * 8 + 1); LD_A(p0 * 8 + 2);
    px2 k0[4], k1[4], k2[4], k3[4], e1[4], a1[4];
    int bcur = -1;
    px2 pz = pk(0.f, 0.f);
    bool oddc = (c & 1), bit1 = (c & 2);
    int sbase = (c == 0) ? 0 : (c == 1) ? 6 : (c == 2) ? 3 : 9;
    for (int p = p0; p < p1; ++p) {
        int b = p >> 4;
        if (b != bcur) {
            bcur = b;
            LOADOP(k0, g_k + ((size_t)0 * B_ + b) * 64);
            LOADOP(k1, g_k + ((size_t)1 * B_ + b) * 64);
            LOADOP(k2, g_k + ((size_t)2 * B_ + b) * 64);
            LOADOP(k3, g_k + ((size_t)3 * B_ + b) * 64);
            LOADOP(e1, g_e + ((size_t)0 * B_ + b) * 64);
            LOADOP(a1, g_a + ((size_t)0 * B_ + b) * 64);
        }
#pragma unroll
        for (int it = 0; it < 8; ++it) {
            int L = p * 8 + it;
            if (L + 3 < Lend) LD_A(L + 3);
            size_t n = (size_t)L * 32 + warp * 4 + rg;
            float4 A = bufA[it & 3], Bv = bufB[it & 3];
            px2 v[4] = { pk(A.x, A.y), pk(A.z, A.w), pk(Bv.x, Bv.y), pk(Bv.z, Bv.w) };
            px2 d0 = pz, d1 = pz, nr = pz, u2a = pz, u2b = pz, u3a = pz, u3b = pz;
            px2 v1a = pz, v2a = pz, v3a = pz, v4a = pz;
#pragma unroll
            for (int i = 0; i < 4; ++i) {
                px2 ve = fma2(v[i], e1[i], pz);
                d0  = fma2(v[i], k0[i], d0);
                d1  = fma2(v[i], k1[i], d1);
                nr  = fma2(v[i], v[i], nr);
                u2a = fma2(v[i], k2[i], u2a);
                u3a = fma2(v[i], k3[i], u3a);
                u2b = fma2(ve, k2[i], u2b);
                u3b = fma2(ve, k3[i], u3b);
                v1a = fma2(v[i], a1[i], v1a);
                v3a = fma2(ve, a1[i], v3a);
                v2a = fma2(ve, v[i], v2a);
                v4a = fma2(ve, ve, v4a);
            }
            float s[11]; float2 f;
            f = up(d0);  s[0] = f.x + f.y;
            f = up(d1);  s[1] = f.x + f.y;
            f = up(nr);  s[2] = f.x + f.y;
            f = up(u2a); s[3] = f.x + f.y;
            f = up(u2b); s[4] = f.x + f.y;
            f = up(u3a); s[5] = f.x + f.y;
            f = up(u3b); s[6] = f.x + f.y;
            f = up(v1a); s[7] = f.x + f.y;
            f = up(v2a); s[8] = f.x + f.y;
            f = up(v3a); s[9] = f.x + f.y;
            f = up(v4a); s[10] = f.x + f.y;
            // reduce-scatter over 8 lanes (c bits)
#pragma unroll
            for (int t = 0; t < 11; ++t) s[t] += __shfl_xor_sync(0xffffffffu, s[t], 1);
            float kk[6];
            kk[0] = oddc ? s[6]  : s[0];
            kk[1] = oddc ? s[7]  : s[1];
            kk[2] = oddc ? s[8]  : s[2];
            kk[3] = oddc ? s[9]  : s[3];
            kk[4] = oddc ? s[10] : s[4];
            kk[5] = oddc ? s[10] : s[5];
#pragma unroll
            for (int t = 0; t < 6; ++t) kk[t] += __shfl_xor_sync(0xffffffffu, kk[t], 2);
            float m0v = bit1 ? kk[3] : kk[0];
            float m1v = bit1 ? kk[4] : kk[1];
            float m2v = bit1 ? kk[5] : kk[2];
            m0v += __shfl_xor_sync(0xffffffffu, m0v, 4);
            m1v += __shfl_xor_sync(0xffffffffu, m1v, 4);
            m2v += __shfl_xor_sync(0xffffffffu, m2v, 4);
            // classes: c0:{0,1,2} c1:{6,7,8} c2:{3,4,5} c3:{9,10}
            if (c < 4) {
                g_red[(size_t)sbase * RBN + n] = m0v;
                g_red[(size_t)(sbase + 1) * RBN + n] = m1v;
                if (c < 3) g_red[(size_t)(sbase + 2) * RBN + n] = m2v;
            }
        }
    }
}

// ---- Pass C': reads0, reads2, update -> write v2, + 9 reductions ----
// slots: 0:dot4 1:dot5 2:nrm2 3:d6a 4:d6b 5:q1 6:q2 7:p1 8:p2
__global__ __launch_bounds__(256, 2) void passC_kernel(const float* __restrict__ mem0) {
    __shared__ float sred[8][64];
    PASS_HEAD(NPASSBLK);
    const float* wp0 = g_w + 0 * RBN;
    const float* wp1 = g_w + 1 * RBN;
    const float* wp2 = g_w + 2 * RBN;
    const float* wp3 = g_w + 3 * RBN;
    float4 bufA[2], bufB[2];
#define LD_C(L) { size_t n = (size_t)(L) * 32 + warp * 4 + rg;              \
        const float4* p = (const float4*)(mem0 + n * 64 + col0);            \
        bufA[(L) & 1] = __ldcs(p); bufB[(L) & 1] = __ldcs(p + 1); }
    LD_C(p0 * 8);
    px2 k4[4], k5[4], ne1[4], a1[4], ne3[4], a3[4], k6[4], e5[4], a5[4];
    int bcur = -1;
    px2 pz = pk(0.f, 0.f);
    for (int p = p0; p < p1; ++p) {
        int b = p >> 4;
        if (b != bcur) {
            bcur = b;
            LOADOP(k4, g_k + ((size_t)4 * B_ + b) * 64);
            LOADOP(k5, g_k + ((size_t)5 * B_ + b) * 64);
            LOADOPN(ne1, g_e + ((size_t)0 * B_ + b) * 64);
            LOADOP(a1, g_a + ((size_t)0 * B_ + b) * 64);
            LOADOPN(ne3, g_e + ((size_t)1 * B_ + b) * 64);
            LOADOP(a3, g_a + ((size_t)1 * B_ + b) * 64);
            LOADOP(k6, g_k + ((size_t)6 * B_ + b) * 64);
            LOADOP(e5, g_e + ((size_t)2 * B_ + b) * 64);
            LOADOP(a5, g_a + ((size_t)2 * B_ + b) * 64);
        }
        px2 acc0[4] = { pz, pz, pz, pz };
        px2 acc2[4] = { pz, pz, pz, pz };
#pragma unroll
        for (int it = 0; it < 8; ++it) {
            int L = p * 8 + it;
            if (L + 1 < Lend) LD_C(L + 1);
            size_t n = (size_t)L * 32 + warp * 4 + rg;
            float w0 = __ldg(wp0 + n), w1 = __ldg(wp1 + n);
            float w2 = __ldg(wp2 + n), w3 = __ldg(wp3 + n);
            float4 A = bufA[it & 1], Bv = bufB[it & 1];
            px2 v[4] = { pk(A.x, A.y), pk(A.z, A.w), pk(Bv.x, Bv.y), pk(Bv.z, Bv.w) };
            px2 w0p = pk(w0, w0), w1p = pk(w1, w1), w2p = pk(w2, w2), w3p = pk(w3, w3);
            px2 d4 = pz, d5 = pz, nr = pz;
            px2 d6a = pz, d6b = pz, q1 = pz, q2 = pz, p1v = pz, p2v = pz;
#pragma unroll
            for (int i = 0; i < 4; ++i) {
                acc0[i] = fma2(w0p, v[i], acc0[i]);              // reads0 on m0
                px2 t = fma2(ne1[i], v[i], a1[i]);
                px2 m1 = fma2(w1p, t, v[i]);
                acc2[i] = fma2(w2p, m1, acc2[i]);                // reads2 on m1
                px2 t3 = fma2(ne3[i], m1, a3[i]);
                px2 m2 = fma2(w3p, t3, m1);
                v[i] = m2;
                d4 = fma2(m2, k4[i], d4);
                d5 = fma2(m2, k5[i], d5);
                nr = fma2(m2, m2, nr);
                // head-6 reductions on m2
                px2 ve = fma2(m2, e5[i], pz);
                d6a = fma2(m2, k6[i], d6a);
                d6b = fma2(ve, k6[i], d6b);
                q1  = fma2(ve, m2, q1);
                q2  = fma2(ve, ve, q2);
                p1v = fma2(m2, a5[i], p1v);
                p2v = fma2(ve, a5[i], p2v);
            }
            float* po = g_mem + n * 64 + col0;
            float2 f0 = up(v[0]), f1 = up(v[1]);
            __stcs((float4*)po, make_float4(f0.x, f0.y, f1.x, f1.y));
            float2 f2 = up(v[2]), f3 = up(v[3]);
            __stcs((float4*)po + 1, make_float4(f2.x, f2.y, f3.x, f3.y));
            float s[9]; float2 f;
            f = up(d4);  s[0] = f.x + f.y;
            f = up(d5);  s[1] = f.x + f.y;
            f = up(nr);  s[2] = f.x + f.y;
            f = up(d6a); s[3] = f.x + f.y;
            f = up(d6b); s[4] = f.x + f.y;
            f = up(q1);  s[5] = f.x + f.y;
            f = up(q2);  s[6] = f.x + f.y;
            f = up(p1v); s[7] = f.x + f.y;
            f = up(p2v); s[8] = f.x + f.y;
#pragma unroll
            for (int o = 1; o <= 4; o <<= 1)
#pragma unroll
                for (int t = 0; t < 9; ++t) s[t] += __shfl_xor_sync(0xffffffffu, s[t], o);
            // lane-distributed store: lane c stores slot c; lane 0 also stores slot 8
            g_red[(size_t)c * RBN + n] = s[c];
            if (c == 0) g_red[(size_t)8 * RBN + n] = s[8];
        }
        reads_epilogue(acc0, sred, lane, warp, c, tid, p, 0);
        reads_epilogue(acc2, sred, lane, warp, c, tid, p, 1);
    }
}

// ---- Pass E': reads4 = colsum(w4, v2), Sa = colsum(w6, v2), Sb = colsum(w6*w5, v2) ----
__global__ __launch_bounds__(256, 3) void passE_kernel() {
    __shared__ float sred[8][64];
    PASS_HEAD(NPBE);
    const float* wp4 = g_w + 4 * RBN;
    const float* wp5 = g_w + 5 * RBN;
    const float* wp6 = g_w + 6 * RBN;
    float4 bufA[4], bufB[4];
#define LD_E(L) { size_t n = (size_t)(L) * 32 + warp * 4 + rg;              \
        const float4* p = (const float4*)(g_mem + n * 64 + col0);           \
        bufA[(L) & 3] = __ldcs(p); bufB[(L) & 3] = __ldcs(p + 1); }
    LD_E(p0 * 8); LD_E(p0 * 8 + 1);
    for (int p = p0; p < p1; ++p) {
        px2 accR[4], accA[4], accB[4];
#pragma unroll
        for (int i = 0; i < 4; ++i) { accR[i] = pk(0.f, 0.f); accA[i] = pk(0.f, 0.f); accB[i] = pk(0.f, 0.f); }
#pragma unroll
        for (int it = 0; it < 8; ++it) {
            int L = p * 8 + it;
            if (L + 2 < Lend) LD_E(L + 2);
            size_t n = (size_t)L * 32 + warp * 4 + rg;
            float w4 = __ldg(wp4 + n), w5 = __ldg(wp5 + n), w6 = __ldg(wp6 + n);
            float4 A = bufA[it & 3], Bv = bufB[it & 3];
            px2 v[4] = { pk(A.x, A.y), pk(A.z, A.w), pk(Bv.x, Bv.y), pk(Bv.z, Bv.w) };
            px2 w4p = pk(w4, w4), w6p = pk(w6, w6), w65p = pk(w6 * w5, w6 * w5);
#pragma unroll
            for (int i = 0; i < 4; ++i) {
                accR[i] = fma2(w4p, v[i], accR[i]);
                accA[i] = fma2(w6p, v[i], accA[i]);
                accB[i] = fma2(w65p, v[i], accB[i]);
            }
        }
        reads_epilogue(accR, sred, lane, warp, c, tid, p, 2);
        reads_epilogue(accA, sred, lane, warp, c, tid, p, 3);
        reads_epilogue(accB, sred, lane, warp, c, tid, p, 4);
    }
}

// ---------------- finalize helpers ----------------
__device__ __forceinline__ float block_reduce_max(float v, float* sbuf) {
#pragma unroll
    for (int o = 16; o; o >>= 1) v = fmaxf(v, __shfl_xor_sync(0xffffffffu, v, o));
    int lane = threadIdx.x & 31, w = threadIdx.x >> 5;
    if (lane == 0) sbuf[w] = v;
    __syncthreads();
    if (threadIdx.x < 32) {
        float vv = (threadIdx.x < 8) ? sbuf[threadIdx.x] : -3.4e38f;
#pragma unroll
        for (int o = 4; o; o >>= 1) vv = fmaxf(vv, __shfl_xor_sync(0xffffffffu, vv, o));
        if (threadIdx.x == 0) sbuf[0] = vv;
    }
    __syncthreads();
    v = sbuf[0];
    __syncthreads();
    return v;
}
__device__ __forceinline__ float block_reduce_sum(float v, float* sbuf) {
#pragma unroll
    for (int o = 16; o; o >>= 1) v += __shfl_xor_sync(0xffffffffu, v, o);
    int lane = threadIdx.x & 31, w = threadIdx.x >> 5;
    if (lane == 0) sbuf[w] = v;
    __syncthreads();
    if (threadIdx.x < 32) {
        float vv = (threadIdx.x < 8) ? sbuf[threadIdx.x] : 0.f;
#pragma unroll
        for (int o = 4; o; o >>= 1) vv += __shfl_xor_sync(0xffffffffu, vv, o);
        if (threadIdx.x == 0) sbuf[0] = vv;
    }
    __syncthreads();
    v = sbuf[0];
    __syncthreads();
    return v;
}

// softmax/interp/shift/sharpen from per-element score sc[] -> w_hd
__device__ __forceinline__ void fin_core(float* sc, int hd, int b, float gate,
                                         float s0, float s1, float s2, float gamma,
                                         const float* pw, float* sbuf, float* swg) {
    int tid = threadIdx.x;
    float lmax = -3.4e38f;
#pragma unroll
    for (int t = 0; t < 16; ++t) lmax = fmaxf(lmax, sc[t]);
    float bmax = block_reduce_max(lmax, sbuf);
    float lsum = 0.f;
#pragma unroll
    for (int t = 0; t < 16; ++t) { float e = __expf(sc[t] - bmax); sc[t] = e; lsum += e; }
    float bsum = block_reduce_sum(lsum, sbuf);
    float inv = 1.f / bsum;
#pragma unroll
    for (int t = 0; t < 16; ++t) {
        int idx = tid + t * 256;
        swg[idx] = gate * sc[t] * inv + (1.f - gate) * pw[idx];
    }
    __syncthreads();
    float wp[16];
    float lps = 0.f;
#pragma unroll
    for (int t = 0; t < 16; ++t) {
        int idx = tid + t * 256;
        float ws = s0 * swg[(idx + N_ - 1) & (N_ - 1)] + s1 * swg[idx]
                 + s2 * swg[(idx + 1) & (N_ - 1)];
        float p = __powf(ws, gamma);
        wp[t] = p; lps += p;
    }
    float psum = block_reduce_sum(lps, sbuf);
    float invp = 1.f / (psum + EPSV);
    float* wout = g_w + (size_t)hd * RBN + (size_t)b * N_;
#pragma unroll
    for (int t = 0; t < 16; ++t) {
        int idx = tid + t * 256;
        wout[idx] = wp[t] * invp;
    }
}

// fin for heads 0-3 after pass A: 0,1 direct; 2,3 assembled from pass-A reductions
__global__ void finA_kernel(const float* __restrict__ prevW) {
    __shared__ float swg[N_];
    __shared__ float sbuf[8];
    int b = blockIdx.x;
    int hd = blockIdx.y;          // 0..3
    int tid = threadIdx.x;
    int hb = hd * B_ + b;
    float knorm = g_knorm[hb], beta = g_beta[hb], gate = g_gate[hb], gamma = g_gamma[hb];
    float s0 = g_s[hb * 3 + 0], s1 = g_s[hb * 3 + 1], s2 = g_s[hb * 3 + 2];
    const float* pw = prevW + ((size_t)hd * B_ + b) * N_;
    const size_t base = (size_t)b * N_;
    float sc[16];
    if (hd < 2) {
        const float* dot = hd ? RED(1) : RED(0);
        const float* nrm = RED(2);
#pragma unroll
        for (int t = 0; t < 16; ++t) {
            int idx = tid + t * 256;
            float d = dot[base + idx];
            float nr = nrm[base + idx];
            sc[t] = beta * d / (sqrtf(nr) * knorm + EPSV);
        }
    } else {
        int hh = hd - 2;
        float Ax = hh ? g_A3[b] : g_A2[b];
        float Aaa = g_Aaa[b];
        const float* ua = hh ? RED(5) : RED(3);
        const float* ub = hh ? RED(6) : RED(4);
        const float* nrm = RED(2);
        const float* r5 = RED(7); const float* r6 = RED(8);
        const float* r7 = RED(9); const float* r8 = RED(10);
        const float* wp1 = g_w + 1 * RBN + base;
#pragma unroll
        for (int t = 0; t < 16; ++t) {
            int idx = tid + t * 256;
            float w1 = wp1[idx];
            float d = ua[base + idx] + w1 * (Ax - ub[base + idx]);
            float nrm1 = nrm[base + idx]
                       + 2.f * w1 * (r5[base + idx] - r6[base + idx])
                       + w1 * w1 * (Aaa - 2.f * r7[base + idx] + r8[base + idx]);
            nrm1 = fmaxf(nrm1, 0.f);
            sc[t] = beta * d / (sqrtf(nrm1) * knorm + EPSV);
        }
    }
    fin_core(sc, hd, b, gate, s0, s1, s2, gamma, pw, sbuf, swg);
}

__global__ void fin_kernel(int head0, const float* __restrict__ prevW) {
    __shared__ float swg[N_];
    __shared__ float sbuf[8];
    int b = blockIdx.x;
    int hh = blockIdx.y;
    int hd = head0 + hh;
    int tid = threadIdx.x;
    const float* dot = hh ? RED(1) : RED(0);
    const float* nrm = RED(2);
    int hb = hd * B_ + b;
    float knorm = g_knorm[hb], beta = g_beta[hb], gate = g_gate[hb], gamma = g_gamma[hb];
    float s0 = g_s[hb * 3 + 0], s1 = g_s[hb * 3 + 1], s2 = g_s[hb * 3 + 2];
    const float* pw = prevW + ((size_t)hd * B_ + b) * N_;
    const size_t base = (size_t)b * N_;
    float sc[16];
#pragma unroll
    for (int t = 0; t < 16; ++t) {
        int idx = tid + t * 256;
        float d = dot[base + idx];
        float nr = nrm[base + idx];
        sc[t] = beta * d / (sqrtf(nr) * knorm + EPSV);
    }
    fin_core(sc, hd, b, gate, s0, s1, s2, gamma, pw, sbuf, swg);
}

// fin for head 6: assemble dot6/nrm3 from pass-C' reductions + w5; also T[b] = sum w6 w5
// slots: d6a=3, d6b=4, q0=nrm2=2, q1=5, q2=6, p1=7, p2=8
__global__ void fin6_kernel(const float* __restrict__ prevW) {
    __shared__ float swg[N_];
    __shared__ float sbuf[8];
    int b = blockIdx.x;
    int tid = threadIdx.x;
    const int hd = 6;
    int hb = hd * B_ + b;
    float knorm = g_knorm[hb], beta = g_beta[hb], gate = g_gate[hb], gamma = g_gamma[hb];
    float s0 = g_s[hb * 3 + 0], s1 = g_s[hb * 3 + 1], s2 = g_s[hb * 3 + 2];
    float ak = g_ak[b], aa = g_aa[b];
    const float* pw = prevW + ((size_t)hd * B_ + b) * N_;
    const float* wp5 = g_w + 5 * RBN + (size_t)b * N_;
    const size_t base = (size_t)b * N_;
    const float* d6ap = RED(3); const float* d6bp = RED(4);
    const float* q0p = RED(2);  const float* q1p = RED(5);
    const float* q2p = RED(6);  const float* p1p = RED(7);
    const float* p2p = RED(8);
    float sc[16];
#pragma unroll
    for (int t = 0; t < 16; ++t) {
        int idx = tid + t * 256;
        float w5 = wp5[idx];
        float d6 = d6ap[base + idx] + w5 * (ak - d6bp[base + idx]);
        float q0 = q0p[base + idx];
        float q1 = q1p[base + idx], q2 = q2p[base + idx];
        float p1 = p1p[base + idx], p2 = p2p[base + idx];
        float nrm3 = q0 + w5 * (-2.f * q1 + 2.f * p1) + w5 * w5 * (q2 - 2.f * p2 + aa);
        nrm3 = fmaxf(nrm3, 0.f);
        sc[t] = beta * d6 / (sqrtf(nrm3) * knorm + EPSV);
    }
    fin_core(sc, hd, b, gate, s0, s1, s2, gamma, pw, sbuf, swg);
    // T[b] = sum_n w6 w5
    const float* wout = g_w + 6 * RBN + base;
    float lt = 0.f;
#pragma unroll
    for (int t = 0; t < 16; ++t) {
        int idx = tid + t * 256;
        lt += wout[idx] * wp5[idx];
    }
    float T = block_reduce_sum(lt, sbuf);
    if (tid == 0) g_T[b] = T;
}

// ---------------- build state = [h | reads0 | reads2 | reads4 | reads6] ----------------
__global__ void build_state_kernel() {
    int b = blockIdx.x;
    for (int j = threadIdx.x; j < 768; j += blockDim.x) {
        float v;
        if (j < 512) v = g_h[(size_t)b * C_ + j];
        else {
            int ri = (j - 512) >> 6, m = (j - 512) & 63;
            if (ri < 3) {
                float s = 0.f;
                const float* rp = g_rpart + (size_t)ri * B_ * 16 * 64 + (size_t)b * 16 * 64 + m;
#pragma unroll
                for (int cc = 0; cc < 16; ++cc) s += rp[cc * 64];
                v = s;
            } else {
                float sa = 0.f, sb = 0.f;
                const float* rpa = g_rpart + (size_t)3 * B_ * 16 * 64 + (size_t)b * 16 * 64 + m;
                const float* rpb = g_rpart + (size_t)4 * B_ * 16 * 64 + (size_t)b * 16 * 64 + m;
#pragma unroll
                for (int cc = 0; cc < 16; ++cc) { sa += rpa[cc * 64]; sb += rpb[cc * 64]; }
                float e5 = g_e[((size_t)2 * B_ + b) * 64 + m];
                float a5 = g_a[((size_t)2 * B_ + b) * 64 + m];
                v = sa - e5 * sb + g_T[b] * a5;
            }
        }
        g_state[(size_t)b * 768 + j] = v;
    }
}

// ---------------- host ----------------
extern "C" void kernel_launch(void* const* d_in, const int* in_sizes, int n_in,
                              void* d_out, int out_size) {
    const float* in_data      = (const float*)d_in[0];
    const float* memory       = (const float*)d_in[1];
    const float* h0           = (const float*)d_in[2];
    const float* c0           = (const float*)d_in[3];
    const float* prev_weights = (const float*)d_in[4];
    const float* prev_reads   = (const float*)d_in[5];
    const float* W_ih         = (const float*)d_in[6];
    const float* b_ih         = (const float*)d_in[7];
    const float* W_hh         = (const float*)d_in[8];
    const float* b_hh         = (const float*)d_in[9];
    const float* W_out        = (const float*)d_in[10];
    const float* b_out        = (const float*)d_in[11];
    const float* W_addr       = (const float*)d_in[12];
    const float* b_addr       = (const float*)d_in[13];
    const float* W_ea         = (const float*)d_in[14];
    const float* b_ea         = (const float*)d_in[15];
    float* outp = (float*)d_out;

    // controller (split-K GEMMs)
    build_x_kernel<<<(B_ * 320 + 255) / 256, 256>>>(in_data, prev_reads);
    gates_gemm_kernel<<<dim3(2048 / 64, B_ / 64, 4), 256>>>(h0, W_ih, W_hh);
    lstm_kernel<<<(B_ * C_ + 255) / 256, 256>>>(c0, b_ih, b_hh);

    // head parameters (trimmed N=874; split-K 8)
    headpe_gemm_kernel<<<dim3((PEN + 63) / 64, B_ / 64, 8), 256>>>(W_addr, W_ea);
    head_act_kernel<<<B_, 256>>>(b_addr, b_ea);

    passA_kernel<<<NPASSBLK, 256>>>(memory);
    finA_kernel<<<dim3(B_, 4), 256>>>(prev_weights);       // heads 0-3
    passC_kernel<<<NPASSBLK, 256>>>(memory);               // writes v2 + all head-4/5/6 reductions
    fin_kernel<<<dim3(B_, 2), 256>>>(4, prev_weights);     // heads 4,5
    fin6_kernel<<<B_, 256>>>(prev_weights);                // head 6 (needs w5)
    passE_kernel<<<NPBE, 256>>>();                         // reads4 + Sa + Sb on v2

    // output
    build_state_kernel<<<B_, 256>>>();
    out_gemm_kernel<<<dim3(1, B_ / 32, 4), 256>>>(W_out);
    out_fin_kernel<<<(B_ * 64 + 255) / 256, 256>>>(b_out, outp);
}

// round 14
// speedup vs baseline: 1.0596x; 1.0596x over previous
#include <cuda_runtime.h>
#include <cstdint>

#define B_  256
#define N_  4096
#define M_  64
#define C_  512
#define EPSV 1e-8f
#define NPASSBLK 296
#define NPAIRS   4096
#define RBN ((size_t)B_ * N_)
#define PEN 874
#define PE1 490
#define PEB ((size_t)B_ * PEN)
#define GTB ((size_t)B_ * 2048)
#define OTB ((size_t)B_ * 64)

// ---------------- packed f32x2 helpers (sm_103a FFMA2) ----------------
struct px2 { unsigned long long u; };
__device__ __forceinline__ px2 pk(float x, float y) {
    px2 r; asm("mov.b64 %0,{%1,%2};" : "=l"(r.u) : "f"(x), "f"(y)); return r;
}
__device__ __forceinline__ float2 up(px2 a) {
    float2 f; asm("mov.b64 {%0,%1},%2;" : "=f"(f.x), "=f"(f.y) : "l"(a.u)); return f;
}
__device__ __forceinline__ px2 fma2(px2 a, px2 b, px2 c) {
    px2 r; asm("fma.rn.f32x2 %0,%1,%2,%3;" : "=l"(r.u) : "l"(a.u), "l"(b.u), "l"(c.u)); return r;
}

// ---------------- device scratch ----------------
__device__ __align__(16) float g_mem[(size_t)B_ * N_ * M_];      // v2 working memory (written once, pass C)
__device__ __align__(16) float g_x[B_ * 320];
__device__ __align__(16) float g_gates4[4 * GTB];
__device__ __align__(16) float g_c[B_ * C_];
__device__ __align__(16) float g_h[B_ * C_];
__device__ __align__(16) float g_pe16[16 * PEB];
__device__ __align__(16) float g_out4[4 * OTB];
__device__ __align__(16) float g_k[7 * B_ * M_];
__device__ float g_knorm[7 * B_];
__device__ float g_beta[7 * B_];
__device__ float g_gate[7 * B_];
__device__ float g_s[7 * B_ * 3];
__device__ float g_gamma[7 * B_];
__device__ __align__(16) float g_e[3 * B_ * M_];
__device__ __align__(16) float g_a[3 * B_ * M_];
__device__ __align__(16) float g_red[11 * RBN];                  // reduction slots
__device__ __align__(16) float g_w[7 * RBN];                     // per-head weights, slot = head index
__device__ __align__(16) float g_rpart[5 * B_ * 16 * M_];        // colsum partials: reads0,2,4, Sa, Sb
__device__ float g_ak[B_];    // a5 . k6
__device__ float g_aa[B_];    // |a5|^2
__device__ float g_A2[B_];    // a1 . k2
__device__ float g_A3[B_];    // a1 . k3
__device__ float g_Aaa[B_];   // |a1|^2
__device__ float g_T[B_];     // sum_n w6 w5
__device__ __align__(16) float g_state[B_ * 768];

#define RED(i) (g_red + (size_t)(i) * RBN)

// ---------------- helpers ----------------
__device__ __forceinline__ float sigf(float x) { return 1.f / (1.f + expf(-x)); }
__device__ __forceinline__ float softplusf(float x) { return x > 20.f ? x : log1pf(expf(x)); }

// ---------------- build x = [in_data | prev_reads 0..3] ----------------
__global__ void build_x_kernel(const float* __restrict__ in_data,
                               const float* __restrict__ prev_reads) {
    int idx = blockIdx.x * blockDim.x + threadIdx.x;
    if (idx >= B_ * 320) return;
    int b = idx / 320, j = idx % 320;
    float v;
    if (j < 64) v = in_data[b * 64 + j];
    else { int i = (j - 64) >> 6, m = (j - 64) & 63; v = prev_reads[((size_t)i * B_ + b) * 64 + m]; }
    g_x[idx] = v;
}

// gates GEMM, 64x64 tile / 4x4 microtile, split-K 4: partials -> g_gates4[z]
__global__ void gates_gemm_kernel(const float* __restrict__ h0,
                                  const float* __restrict__ Wih,
                                  const float* __restrict__ Whh) {
    __shared__ __align__(16) float As[16][64];
    __shared__ __align__(16) float Bs[16][64];
    int tid = threadIdx.x;
    int z = blockIdx.z;
    const float* A = (z < 2) ? g_x : h0;
    const float* Bw = (z < 2) ? Wih : Whh;
    int K = (z < 2) ? 320 : 512;
    int kbeg = (z == 0) ? 0 : (z == 1) ? 160 : (z == 2) ? 0 : 256;
    int kend = (z == 0) ? 160 : (z == 1) ? 320 : (z == 2) ? 256 : 512;
    int m0 = blockIdx.y * 64, n0 = blockIdx.x * 64;
    int l_r = tid >> 2, l_k = (tid & 3) * 4;
    int ty = tid >> 4, tx = tid & 15;
    float acc[4][4] = {};
    const float* ap = A + (size_t)(m0 + l_r) * K + l_k;
    const float* bp = Bw + (size_t)(n0 + l_r) * K + l_k;
    float4 av = *(const float4*)(ap + kbeg);
    float4 bv = *(const float4*)(bp + kbeg);
    for (int k0 = kbeg; k0 < kend; k0 += 16) {
        __syncthreads();
        As[l_k + 0][l_r] = av.x; As[l_k + 1][l_r] = av.y;
        As[l_k + 2][l_r] = av.z; As[l_k + 3][l_r] = av.w;
        Bs[l_k + 0][l_r] = bv.x; Bs[l_k + 1][l_r] = bv.y;
        Bs[l_k + 2][l_r] = bv.z; Bs[l_k + 3][l_r] = bv.w;
        if (k0 + 16 < kend) {
            av = *(const float4*)(ap + k0 + 16);
            bv = *(const float4*)(bp + k0 + 16);
        }
        __syncthreads();
#pragma unroll
        for (int kk = 0; kk < 16; kk++) {
            float4 a = *(const float4*)&As[kk][ty << 2];
            float4 b = *(const float4*)&Bs[kk][tx << 2];
            acc[0][0] += a.x * b.x; acc[0][1] += a.x * b.y; acc[0][2] += a.x * b.z; acc[0][3] += a.x * b.w;
            acc[1][0] += a.y * b.x; acc[1][1] += a.y * b.y; acc[1][2] += a.y * b.z; acc[1][3] += a.y * b.w;
            acc[2][0] += a.z * b.x; acc[2][1] += a.z * b.y; acc[2][2] += a.z * b.z; acc[2][3] += a.z * b.w;
            acc[3][0] += a.w * b.x; acc[3][1] += a.w * b.y; acc[3][2] += a.w * b.z; acc[3][3] += a.w * b.w;
        }
    }
    float* outp = g_gates4 + (size_t)z * GTB;
#pragma unroll
    for (int i = 0; i < 4; i++) {
        int m = m0 + (ty << 2) + i;
#pragma unroll
        for (int j = 0; j < 4; j++) {
            int n = n0 + (tx << 2) + j;
            outp[(size_t)m * 2048 + n] = acc[i][j];
        }
    }
}

// head-param GEMM, trimmed N=874, 64x64 tile / 4x4 microtile, split-K 16 x 32
__global__ void headpe_gemm_kernel(const float* __restrict__ Wa,
                                   const float* __restrict__ We) {
    __shared__ __align__(16) float As[16][64];
    __shared__ __align__(16) float Bs[16][64];
    const int K = 512;
    int tid = threadIdx.x;
    int z = blockIdx.z;
    int kbeg = z * 32, kend = kbeg + 32;
    int m0 = blockIdx.y * 64, n0 = blockIdx.x * 64;
    int l_r = tid >> 2, l_k = (tid & 3) * 4;
    int ty = tid >> 4, tx = tid & 15;
    int brow = n0 + l_r;
    const float* browp = (brow < PE1) ? (Wa + (size_t)brow * K)
                                      : (We + (size_t)(brow - PE1) * K);
    bool bok = (brow < PEN);
    const float* ap = g_c + (size_t)(m0 + l_r) * K + l_k;
    float4 av = *(const float4*)(ap + kbeg);
    float4 bv = bok ? *(const float4*)(browp + l_k + kbeg) : make_float4(0.f, 0.f, 0.f, 0.f);
    float acc[4][4] = {};
    for (int k0 = kbeg; k0 < kend; k0 += 16) {
        __syncthreads();
        As[l_k + 0][l_r] = av.x; As[l_k + 1][l_r] = av.y;
        As[l_k + 2][l_r] = av.z; As[l_k + 3][l_r] = av.w;
        Bs[l_k + 0][l_r] = bv.x; Bs[l_k + 1][l_r] = bv.y;
        Bs[l_k + 2][l_r] = bv.z; Bs[l_k + 3][l_r] = bv.w;
        if (k0 + 16 < kend) {
            av = *(const float4*)(ap + k0 + 16);
            bv = bok ? *(const float4*)(browp + l_k + k0 + 16) : make_float4(0.f, 0.f, 0.f, 0.f);
        }
        __syncthreads();
#pragma unroll
        for (int kk = 0; kk < 16; kk++) {
            float4 a = *(const float4*)&As[kk][ty << 2];
            float4 b = *(const float4*)&Bs[kk][tx << 2];
            acc[0][0] += a.x * b.x; acc[0][1] += a.x * b.y; acc[0][2] += a.x * b.z; acc[0][3] += a.x * b.w;
            acc[1][0] += a.y * b.x; acc[1][1] += a.y * b.y; acc[1][2] += a.y * b.z; acc[1][3] += a.y * b.w;
            acc[2][0] += a.z * b.x; acc[2][1] += a.z * b.y; acc[2][2] += a.z * b.z; acc[2][3] += a.z * b.w;
            acc[3][0] += a.w * b.x; acc[3][1] += a.w * b.y; acc[3][2] += a.w * b.z; acc[3][3] += a.w * b.w;
        }
    }
    float* outp = g_pe16 + (size_t)z * PEB;
#pragma unroll
    for (int i = 0; i < 4; i++) {
        int m = m0 + (ty << 2) + i;
#pragma unroll
        for (int j = 0; j < 4; j++) {
            int n = n0 + (tx << 2) + j;
            if (n < PEN) outp[(size_t)m * PEN + n] = acc[i][j];
        }
    }
}

// output GEMM, split-K 4 x 192: partials -> g_out4[z]   (N=64, K=768)
__global__ void out_gemm_kernel(const float* __restrict__ Wo) {
    __shared__ __align__(16) float As[16][32];
    __shared__ __align__(16) float Bs[16][64];
    const int NN = 64, K = 768;
    int tid = threadIdx.x;
    int z = blockIdx.z;
    int kbeg = z * 192, kend = kbeg + 192;
    int m0 = blockIdx.y * 32, n0 = 0;
    int la_r = tid >> 3, la_k = (tid & 7) * 2;
    int lb_r = tid >> 2, lb_k = (tid & 3) * 4;
    int ty = tid >> 4, tx = tid & 15;
    const float* ap = g_state + (size_t)(m0 + la_r) * K + la_k;
    const float* bp = Wo + (size_t)(n0 + lb_r) * K + lb_k;
    float2 av = *(const float2*)(ap + kbeg);
    float4 bv = *(const float4*)(bp + kbeg);
    float acc[2][4] = {};
    for (int k0 = kbeg; k0 < kend; k0 += 16) {
        __syncthreads();
        As[la_k][la_r] = av.x; As[la_k + 1][la_r] = av.y;
        Bs[lb_k + 0][lb_r] = bv.x; Bs[lb_k + 1][lb_r] = bv.y;
        Bs[lb_k + 2][lb_r] = bv.z; Bs[lb_k + 3][lb_r] = bv.w;
        if (k0 + 16 < kend) {
            av = *(const float2*)(ap + k0 + 16);
            bv = *(const float4*)(bp + k0 + 16);
        }
        __syncthreads();
#pragma unroll
        for (int kk = 0; kk < 16; kk++) {
            float2 a = *(const float2*)&As[kk][ty << 1];
            float4 b = *(const float4*)&Bs[kk][tx << 2];
            acc[0][0] += a.x * b.x; acc[0][1] += a.x * b.y; acc[0][2] += a.x * b.z; acc[0][3] += a.x * b.w;
            acc[1][0] += a.y * b.x; acc[1][1] += a.y * b.y; acc[1][2] += a.y * b.z; acc[1][3] += a.y * b.w;
        }
    }
    float* outp = g_out4 + (size_t)z * OTB;
#pragma unroll
    for (int i = 0; i < 2; i++) {
        int m = m0 + (ty << 1) + i;
#pragma unroll
        for (int j = 0; j < 4; j++) {
            int n = n0 + (tx << 2) + j;
            outp[(size_t)m * NN + n] = acc[i][j];
        }
    }
}

// out finalize: sum split-K partials + bias, sigmoid
__global__ void out_fin_kernel(const float* __restrict__ bo, float* __restrict__ C) {
    int idx = blockIdx.x * 256 + threadIdx.x;
    if (idx >= B_ * 64) return;
    int n = idx & 63;
    float s = g_out4[idx] + g_out4[OTB + idx] + g_out4[2 * OTB + idx] + g_out4[3 * OTB + idx];
    C[idx] = sigf(s + bo[n]);
}

// ---------------- LSTM pointwise (sums gates split-K partials + biases) ----------------
__global__ void lstm_kernel(const float* __restrict__ c0,
                            const float* __restrict__ bih, const float* __restrict__ bhh) {
    int idx = blockIdx.x * blockDim.x + threadIdx.x;
    if (idx >= B_ * C_) return;
    int b = idx / C_, j = idx % C_;
    size_t base = (size_t)b * 2048;
    float g4[4];
#pragma unroll
    for (int gi = 0; gi < 4; ++gi) {
        size_t o = base + gi * 512 + j;
        g4[gi] = g_gates4[o] + g_gates4[GTB + o] + g_gates4[2 * GTB + o] + g_gates4[3 * GTB + o]
               + bih[gi * 512 + j] + bhh[gi * 512 + j];
    }
    float c = sigf(g4[1]) * c0[idx] + sigf(g4[0]) * tanhf(g4[2]);
    g_c[idx] = c;
    g_h[idx] = sigf(g4[3]) * tanhf(c);
}

// ---------------- head activations (stage pe = sum 16 partials + bias into smem) ----------------
// trimmed layout: [0,490): addr heads 0..6 (70 each); [490,874): ea heads 0..2 (128 each)
__global__ void head_act_kernel(const float* __restrict__ ba, const float* __restrict__ be) {
    __shared__ float spe[PEN];
    int b = blockIdx.x;
    int tid = threadIdx.x;
    for (int j = tid; j < PEN; j += 256) {
        size_t o = (size_t)b * PEN + j;
        float bias = (j < PE1) ? ba[j] : be[j - PE1];
        float s = 0.f;
#pragma unroll
        for (int zz = 0; zz < 16; ++zz) s += g_pe16[(size_t)zz * PEB + o];
        spe[j] = s + bias;
    }
    __syncthreads();
    int wid = tid >> 5, lane = tid & 31;
    if (wid < 7) {
        int hd = wid;
        const float* p = spe + hd * 70;
        float ssq = 0.f;
        for (int j = lane; j < 64; j += 32) {
            float kv = tanhf(p[j]);
            g_k[((size_t)hd * B_ + b) * 64 + j] = kv;
            ssq += kv * kv;
        }
#pragma unroll
        for (int o = 16; o; o >>= 1) ssq += __shfl_xor_sync(0xffffffffu, ssq, o);
        if (lane == 0) {
            int hb = hd * B_ + b;
            g_knorm[hb] = sqrtf(ssq);
            g_beta[hb] = softplusf(p[64]);
            g_gate[hb] = sigf(p[65]);
            float s0 = p[66], s1 = p[67], s2 = p[68];
            float mx = fmaxf(s0, fmaxf(s1, s2));
            float e0 = expf(s0 - mx), e1 = expf(s1 - mx), e2 = expf(s2 - mx);
            float inv = 1.f / (e0 + e1 + e2);
            g_s[hb * 3 + 0] = e0 * inv; g_s[hb * 3 + 1] = e1 * inv; g_s[hb * 3 + 2] = e2 * inv;
            g_gamma[hb] = 1.f + softplusf(p[69]);
        }
    } else {
        for (int wh = 0; wh < 3; ++wh) {
            const float* ea = spe + PE1 + wh * 128;
            for (int j = lane; j < 64; j += 32) {
                g_e[((size_t)wh * B_ + b) * 64 + j] = sigf(ea[j]);
                g_a[((size_t)wh * B_ + b) * 64 + j] = tanhf(ea[64 + j]);
            }
        }
        const float* ea2 = spe + PE1 + 2 * 128;
        const float* ea0 = spe + PE1 + 0 * 128;
        const float* p6  = spe + 6 * 70;
        const float* p2  = spe + 2 * 70;
        const float* p3  = spe + 3 * 70;
        float pak = 0.f, paa = 0.f, pa2 = 0.f, pa3 = 0.f, p11 = 0.f;
        for (int j = lane; j < 64; j += 32) {
            float a5v = tanhf(ea2[64 + j]);
            float k6v = tanhf(p6[j]);
            float a1v = tanhf(ea0[64 + j]);
            float k2v = tanhf(p2[j]);
            float k3v = tanhf(p3[j]);
            pak += a5v * k6v; paa += a5v * a5v;
            pa2 += a1v * k2v; pa3 += a1v * k3v; p11 += a1v * a1v;
        }
#pragma unroll
        for (int o = 16; o; o >>= 1) {
            pak += __shfl_xor_sync(0xffffffffu, pak, o);
            paa += __shfl_xor_sync(0xffffffffu, paa, o);
            pa2 += __shfl_xor_sync(0xffffffffu, pa2, o);
            pa3 += __shfl_xor_sync(0xffffffffu, pa3, o);
            p11 += __shfl_xor_sync(0xffffffffu, p11, o);
        }
        if (lane == 0) {
            g_ak[b] = pak; g_aa[b] = paa;
            g_A2[b] = pa2; g_A3[b] = pa3; g_Aaa[b] = p11;
        }
    }
}

// =================== persistent grid-stride memory passes ===================
#define PASS_HEAD()                                                         \
    int tid = threadIdx.x, lane = tid & 31, warp = tid >> 5;                \
    int c = lane & 7, rg = lane >> 3, col0 = c * 8;                         \
    int p0 = (NPAIRS * blockIdx.x) / NPASSBLK;                              \
    int p1 = (NPAIRS * (blockIdx.x + 1)) / NPASSBLK;                        \
    int Lend = p1 * 8;

#define LOADOP(dst, baseptr) {                                              \
    const float4* _q = (const float4*)((baseptr) + col0);                   \
    float4 _u0 = __ldg(_q), _u1 = __ldg(_q + 1);                            \
    dst[0] = pk(_u0.x, _u0.y); dst[1] = pk(_u0.z, _u0.w);                   \
    dst[2] = pk(_u1.x, _u1.y); dst[3] = pk(_u1.z, _u1.w); }
#define LOADOPN(dst, baseptr) {                                             \
    const float4* _q = (const float4*)((baseptr) + col0);                   \
    float4 _u0 = __ldg(_q), _u1 = __ldg(_q + 1);                            \
    dst[0] = pk(-_u0.x, -_u0.y); dst[1] = pk(-_u0.z, -_u0.w);               \
    dst[2] = pk(-_u1.x, -_u1.y); dst[3] = pk(-_u1.z, -_u1.w); }

__device__ __forceinline__ void reads_epilogue(px2* acc, float (*sred)[64],
                                               int lane, int warp, int c, int tid,
                                               int pair, int slot) {
    float va[8];
#pragma unroll
    for (int i = 0; i < 4; ++i) { float2 f = up(acc[i]); va[2 * i] = f.x; va[2 * i + 1] = f.y; }
#pragma unroll
    for (int t = 0; t < 8; ++t) {
        va[t] += __shfl_xor_sync(0xffffffffu, va[t], 8);
        va[t] += __shfl_xor_sync(0xffffffffu, va[t], 16);
    }
    if (lane < 8) {
#pragma unroll
        for (int t = 0; t < 8; ++t) sred[warp][c * 8 + t] = va[t];
    }
    __syncthreads();
    if (tid < 64) {
        float s = 0.f;
#pragma unroll
        for (int wv = 0; wv < 8; ++wv) s += sred[wv][tid];
        g_rpart[(size_t)slot * B_ * 16 * 64 + (size_t)pair * 64 + tid] = s;
    }
    __syncthreads();
}

// ---- Pass A: 11 reductions on mem0 (heads 0-3 material), reduce-scatter ----
// slots: 0:dot0 1:dot1 2:nrm0 3:u2a 4:u2b 5:u3a 6:u3b 7:v1a 8:v2a 9:v3a 10:v4a
__global__ __launch_bounds__(256, 2) void passA_kernel(const float* __restrict__ mem0) {
    PASS_HEAD();
    float4 bufA[4], bufB[4];
#define LD_A(L) { size_t n = (size_t)(L) * 32 + warp * 4 + rg;              \
        const float4* p = (const float4*)(mem0 + n * 64 + col0);            \
        bufA[(L) & 3] = __ldcs(p); bufB[(L) & 3] = __ldcs(p + 1); }
    LD_A(p0 * 8); LD_A(p0 * 8 + 1); LD_A(p0 * 8 + 2);
    px2 k0[4], k1[4], k2[4], k3[4], e1[4], a1[4];
    int bcur = -1;
    px2 pz = pk(0.f, 0.f);
    bool oddc = (c & 1), bit1 = (c & 2);
    int sbase = (c == 0) ? 0 : (c == 1) ? 6 : (c == 2) ? 3 : 9;
    for (int p = p0; p < p1; ++p) {
        int b = p >> 4;
        if (b != bcur) {
            bcur = b;
            LOADOP(k0, g_k + ((size_t)0 * B_ + b) * 64);
            LOADOP(k1, g_k + ((size_t)1 * B_ + b) * 64);
            LOADOP(k2, g_k + ((size_t)2 * B_ + b) * 64);
            LOADOP(k3, g_k + ((size_t)3 * B_ + b) * 64);
            LOADOP(e1, g_e + ((size_t)0 * B_ + b) * 64);
            LOADOP(a1, g_a + ((size_t)0 * B_ + b) * 64);
        }
#pragma unroll
        for (int it = 0; it < 8; ++it) {
            int L = p * 8 + it;
            if (L + 3 < Lend) LD_A(L + 3);
            size_t n = (size_t)L * 32 + warp * 4 + rg;
            float4 A = bufA[it & 3], Bv = bufB[it & 3];
            px2 v[4] = { pk(A.x, A.y), pk(A.z, A.w), pk(Bv.x, Bv.y), pk(Bv.z, Bv.w) };
            px2 d0 = pz, d1 = pz, nr = pz, u2a = pz, u2b = pz, u3a = pz, u3b = pz;
            px2 v1a = pz, v2a = pz, v3a = pz, v4a = pz;
#pragma unroll
            for (int i = 0; i < 4; ++i) {
                px2 ve = fma2(v[i], e1[i], pz);
                d0  = fma2(v[i], k0[i], d0);
                d1  = fma2(v[i], k1[i], d1);
                nr  = fma2(v[i], v[i], nr);
                u2a = fma2(v[i], k2[i], u2a);
                u3a = fma2(v[i], k3[i], u3a);
                u2b = fma2(ve, k2[i], u2b);
                u3b = fma2(ve, k3[i], u3b);
                v1a = fma2(v[i], a1[i], v1a);
                v3a = fma2(ve, a1[i], v3a);
                v2a = fma2(ve, v[i], v2a);
                v4a = fma2(ve, ve, v4a);
            }
            float s[11]; float2 f;
            f = up(d0);  s[0] = f.x + f.y;
            f = up(d1);  s[1] = f.x + f.y;
            f = up(nr);  s[2] = f.x + f.y;
            f = up(u2a); s[3] = f.x + f.y;
            f = up(u2b); s[4] = f.x + f.y;
            f = up(u3a); s[5] = f.x + f.y;
            f = up(u3b); s[6] = f.x + f.y;
            f = up(v1a); s[7] = f.x + f.y;
            f = up(v2a); s[8] = f.x + f.y;
            f = up(v3a); s[9] = f.x + f.y;
            f = up(v4a); s[10] = f.x + f.y;
            // reduce-scatter over 8 lanes (c bits)
#pragma unroll
            for (int t = 0; t < 11; ++t) s[t] += __shfl_xor_sync(0xffffffffu, s[t], 1);
            float kk[6];
            kk[0] = oddc ? s[6]  : s[0];
            kk[1] = oddc ? s[7]  : s[1];
            kk[2] = oddc ? s[8]  : s[2];
            kk[3] = oddc ? s[9]  : s[3];
            kk[4] = oddc ? s[10] : s[4];
            kk[5] = oddc ? s[10] : s[5];
#pragma unroll
            for (int t = 0; t < 6; ++t) kk[t] += __shfl_xor_sync(0xffffffffu, kk[t], 2);
            float m0v = bit1 ? kk[3] : kk[0];
            float m1v = bit1 ? kk[4] : kk[1];
            float m2v = bit1 ? kk[5] : kk[2];
            m0v += __shfl_xor_sync(0xffffffffu, m0v, 4);
            m1v += __shfl_xor_sync(0xffffffffu, m1v, 4);
            m2v += __shfl_xor_sync(0xffffffffu, m2v, 4);
            // classes: c0:{0,1,2} c1:{6,7,8} c2:{3,4,5} c3:{9,10}
            if (c < 4) {
                g_red[(size_t)sbase * RBN + n] = m0v;
                g_red[(size_t)(sbase + 1) * RBN + n] = m1v;
                if (c < 3) g_red[(size_t)(sbase + 2) * RBN + n] = m2v;
            }
        }
    }
}

// ---- Pass C: reads0 (w0,m0), m1 regs, reads2 (w2,m1), update -> write v2, dot4, dot5, nrm2 ----
// slots: 0:dot4 1:dot5 2:nrm2
__global__ __launch_bounds__(256, 2) void passC_kernel(const float* __restrict__ mem0) {
    __shared__ float sred[8][64];
    PASS_HEAD();
    const float* wp0 = g_w + 0 * RBN;
    const float* wp1 = g_w + 1 * RBN;
    const float* wp2 = g_w + 2 * RBN;
    const float* wp3 = g_w + 3 * RBN;
    float4 bufA[4], bufB[4];
#define LD_C(L) { size_t n = (size_t)(L) * 32 + warp * 4 + rg;              \
        const float4* p = (const float4*)(mem0 + n * 64 + col0);            \
        bufA[(L) & 3] = __ldcs(p); bufB[(L) & 3] = __ldcs(p + 1); }
    LD_C(p0 * 8); LD_C(p0 * 8 + 1);
    px2 k4[4], k5[4], ne1[4], a1[4], ne3[4], a3[4];
    int bcur = -1;
    px2 pz = pk(0.f, 0.f);
    for (int p = p0; p < p1; ++p) {
        int b = p >> 4;
        if (b != bcur) {
            bcur = b;
            LOADOP(k4, g_k + ((size_t)4 * B_ + b) * 64);
            LOADOP(k5, g_k + ((size_t)5 * B_ + b) * 64);
            LOADOPN(ne1, g_e + ((size_t)0 * B_ + b) * 64);
            LOADOP(a1, g_a + ((size_t)0 * B_ + b) * 64);
            LOADOPN(ne3, g_e + ((size_t)1 * B_ + b) * 64);
            LOADOP(a3, g_a + ((size_t)1 * B_ + b) * 64);
        }
        px2 acc0[4] = { pz, pz, pz, pz };
        px2 acc2[4] = { pz, pz, pz, pz };
#pragma unroll
        for (int it = 0; it < 8; ++it) {
            int L = p * 8 + it;
            if (L + 2 < Lend) LD_C(L + 2);
            size_t n = (size_t)L * 32 + warp * 4 + rg;
            float w0 = __ldg(wp0 + n), w1 = __ldg(wp1 + n);
            float w2 = __ldg(wp2 + n), w3 = __ldg(wp3 + n);
            float4 A = bufA[it & 3], Bv = bufB[it & 3];
            px2 v[4] = { pk(A.x, A.y), pk(A.z, A.w), pk(Bv.x, Bv.y), pk(Bv.z, Bv.w) };
            px2 w0p = pk(w0, w0), w1p = pk(w1, w1), w2p = pk(w2, w2), w3p = pk(w3, w3);
            px2 d4 = pz, d5 = pz, nr = pz;
#pragma unroll
            for (int i = 0; i < 4; ++i) {
                acc0[i] = fma2(w0p, v[i], acc0[i]);              // reads0 on m0
                px2 t = fma2(ne1[i], v[i], a1[i]);
                px2 m1 = fma2(w1p, t, v[i]);
                acc2[i] = fma2(w2p, m1, acc2[i]);                // reads2 on m1
                px2 t3 = fma2(ne3[i], m1, a3[i]);
                px2 m2 = fma2(w3p, t3, m1);
                v[i] = m2;
                d4 = fma2(m2, k4[i], d4);
                d5 = fma2(m2, k5[i], d5);
                nr = fma2(m2, m2, nr);
            }
            float* po = g_mem + n * 64 + col0;
            float2 f0 = up(v[0]), f1 = up(v[1]);
            __stcs((float4*)po, make_float4(f0.x, f0.y, f1.x, f1.y));
            float2 f2 = up(v[2]), f3 = up(v[3]);
            __stcs((float4*)po + 1, make_float4(f2.x, f2.y, f3.x, f3.y));
            float2 fd4 = up(d4), fd5 = up(d5), fn = up(nr);
            float s0 = fd4.x + fd4.y, s1 = fd5.x + fd5.y, sn = fn.x + fn.y;
#pragma unroll
            for (int o = 1; o <= 4; o <<= 1) {
                s0 += __shfl_xor_sync(0xffffffffu, s0, o);
                s1 += __shfl_xor_sync(0xffffffffu, s1, o);
                sn += __shfl_xor_sync(0xffffffffu, sn, o);
            }
            // lane-distributed store: lane c stores slot c (c<3)
            float outv = (c == 0) ? s0 : (c == 1) ? s1 : sn;
            if (c < 3) g_red[(size_t)c * RBN + n] = outv;
        }
        reads_epilogue(acc0, sred, lane, warp, c, tid, p, 0);
        reads_epilogue(acc2, sred, lane, warp, c, tid, p, 1);
    }
}

// ---- Pass D: reads4 + algebraic reductions for head 6 on v2 (NO memory write) ----
// values: 0:d6a 1:d6b 2:q1 3:q2 4:p1 5:p2 -> slots {0,1,3,4,5,6} (slot2 = nrm2 preserved)
__global__ __launch_bounds__(256, 2) void passD_kernel() {
    __shared__ float sred[8][64];
    PASS_HEAD();
    const float* wp4 = g_w + 4 * RBN;
    float4 bufA[4], bufB[4];
#define LD_D(L) { size_t n = (size_t)(L) * 32 + warp * 4 + rg;              \
        const float4* p = (const float4*)(g_mem + n * 64 + col0);           \
        bufA[(L) & 3] = __ldcs(p); bufB[(L) & 3] = __ldcs(p + 1); }
    LD_D(p0 * 8); LD_D(p0 * 8 + 1); LD_D(p0 * 8 + 2);
    px2 k6[4], ek[4], e5[4], es[4], a5[4], ea[4];
    int bcur = -1;
    px2 pz = pk(0.f, 0.f);
    bool oddc = (c & 1), bit1 = (c & 2);
    // classes: c0:{v0,v1}->slots{0,1}; c1:{v3,v4}->slots{4,5}; c2:{v2}->slot{3}; c3:{v5}->slot{6}
    int slotA = (c == 0) ? 0 : (c == 1) ? 4 : (c == 2) ? 3 : 6;
    int slotB = (c == 0) ? 1 : 5;
    for (int p = p0; p < p1; ++p) {
        int b = p >> 4;
        if (b != bcur) {
            bcur = b;
            float kk[8], ee[8], av[8];
            const float4* qk = (const float4*)(g_k + ((size_t)6 * B_ + b) * 64 + col0);
            const float4* qe = (const float4*)(g_e + ((size_t)2 * B_ + b) * 64 + col0);
            const float4* qa = (const float4*)(g_a + ((size_t)2 * B_ + b) * 64 + col0);
            *(float4*)&kk[0] = __ldg(qk); *(float4*)&kk[4] = __ldg(qk + 1);
            *(float4*)&ee[0] = __ldg(qe); *(float4*)&ee[4] = __ldg(qe + 1);
            *(float4*)&av[0] = __ldg(qa); *(float4*)&av[4] = __ldg(qa + 1);
#pragma unroll
            for (int i = 0; i < 4; ++i) {
                float k0v = kk[2*i], k1v = kk[2*i+1];
                float e0v = ee[2*i], e1v = ee[2*i+1];
                float a0v = av[2*i], a1v = av[2*i+1];
                k6[i] = pk(k0v, k1v);
                e5[i] = pk(e0v, e1v);
                ek[i] = pk(e0v * k0v, e1v * k1v);
                es[i] = pk(e0v * e0v, e1v * e1v);
                a5[i] = pk(a0v, a1v);
                ea[i] = pk(e0v * a0v, e1v * a1v);
            }
        }
        px2 acc[4] = { pz, pz, pz, pz };
#pragma unroll
        for (int it = 0; it < 8; ++it) {
            int L = p * 8 + it;
            if (L + 3 < Lend) LD_D(L + 3);
            size_t n = (size_t)L * 32 + warp * 4 + rg;
            float w4 = __ldg(wp4 + n);
            float4 A = bufA[it & 3], Bv = bufB[it & 3];
            px2 v[4] = { pk(A.x, A.y), pk(A.z, A.w), pk(Bv.x, Bv.y), pk(Bv.z, Bv.w) };
            px2 w4p = pk(w4, w4);
            px2 d6a = pz, d6b = pz, q1 = pz, q2 = pz, p1v = pz, p2v = pz;
#pragma unroll
            for (int i = 0; i < 4; ++i) {
                acc[i] = fma2(w4p, v[i], acc[i]);               // reads4 on m2
                px2 vsq = fma2(v[i], v[i], pz);
                d6a = fma2(v[i], k6[i], d6a);
                d6b = fma2(v[i], ek[i], d6b);
                q1  = fma2(vsq, e5[i], q1);
                q2  = fma2(vsq, es[i], q2);
                p1v = fma2(v[i], a5[i], p1v);
                p2v = fma2(v[i], ea[i], p2v);
            }
            float s[6]; float2 f;
            f = up(d6a); s[0] = f.x + f.y;
            f = up(d6b); s[1] = f.x + f.y;
            f = up(q1);  s[2] = f.x + f.y;
            f = up(q2);  s[3] = f.x + f.y;
            f = up(p1v); s[4] = f.x + f.y;
            f = up(p2v); s[5] = f.x + f.y;
#pragma unroll
            for (int t = 0; t < 6; ++t) s[t] += __shfl_xor_sync(0xffffffffu, s[t], 1);
            float kk0 = oddc ? s[3] : s[0];
            float kk1 = oddc ? s[4] : s[1];
            float kk2 = oddc ? s[5] : s[2];
            kk0 += __shfl_xor_sync(0xffffffffu, kk0, 2);
            kk1 += __shfl_xor_sync(0xffffffffu, kk1, 2);
            kk2 += __shfl_xor_sync(0xffffffffu, kk2, 2);
            float m0v = bit1 ? kk2 : kk0;
            float m1v = bit1 ? kk2 : kk1;   // m1v only valid for c<2 classes
            m0v += __shfl_xor_sync(0xffffffffu, m0v, 4);
            m1v += __shfl_xor_sync(0xffffffffu, m1v, 4);
            if (c < 4) g_red[(size_t)slotA * RBN + n] = m0v;
            if (c < 2) g_red[(size_t)slotB * RBN + n] = m1v;
        }
        reads_epilogue(acc, sred, lane, warp, c, tid, p, 2);
    }
}

// ---- Pass E: Sa = colsum(w6, v2), Sb = colsum(w6*w5, v2) ----
__global__ __launch_bounds__(256, 2) void passE_kernel() {
    __shared__ float sredA[8][64];
    __shared__ float sredB[8][64];
    PASS_HEAD();
    const float* wp5 = g_w + 5 * RBN;
    const float* wp6 = g_w + 6 * RBN;
    float4 bufA[4], bufB[4];
#define LD_E(L) { size_t n = (size_t)(L) * 32 + warp * 4 + rg;              \
        const float4* p = (const float4*)(g_mem + n * 64 + col0);           \
        bufA[(L) & 3] = __ldcs(p); bufB[(L) & 3] = __ldcs(p + 1); }
    LD_E(p0 * 8); LD_E(p0 * 8 + 1); LD_E(p0 * 8 + 2);
    for (int p = p0; p < p1; ++p) {
        px2 accA[4], accB[4];
#pragma unroll
        for (int i = 0; i < 4; ++i) { accA[i] = pk(0.f, 0.f); accB[i] = pk(0.f, 0.f); }
#pragma unroll
        for (int it = 0; it < 8; ++it) {
            int L = p * 8 + it;
            if (L + 3 < Lend) LD_E(L + 3);
            size_t n = (size_t)L * 32 + warp * 4 + rg;
            float w5 = __ldg(wp5 + n), w6 = __ldg(wp6 + n);
            float4 A = bufA[it & 3], Bv = bufB[it & 3];
            px2 v[4] = { pk(A.x, A.y), pk(A.z, A.w), pk(Bv.x, Bv.y), pk(Bv.z, Bv.w) };
            px2 w6p = pk(w6, w6), w65p = pk(w6 * w5, w6 * w5);
#pragma unroll
            for (int i = 0; i < 4; ++i) {
                accA[i] = fma2(w6p, v[i], accA[i]);
                accB[i] = fma2(w65p, v[i], accB[i]);
            }
        }
        reads_epilogue(accA, sredA, lane, warp, c, tid, p, 3);
        reads_epilogue(accB, sredB, lane, warp, c, tid, p, 4);
    }
}

// ---------------- finalize helpers ----------------
__device__ __forceinline__ float block_reduce_max(float v, float* sbuf) {
#pragma unroll
    for (int o = 16; o; o >>= 1) v = fmaxf(v, __shfl_xor_sync(0xffffffffu, v, o));
    int lane = threadIdx.x & 31, w = threadIdx.x >> 5;
    if (lane == 0) sbuf[w] = v;
    __syncthreads();
    if (threadIdx.x < 32) {
        float vv = (threadIdx.x < 8) ? sbuf[threadIdx.x] : -3.4e38f;
#pragma unroll
        for (int o = 4; o; o >>= 1) vv = fmaxf(vv, __shfl_xor_sync(0xffffffffu, vv, o));
        if (threadIdx.x == 0) sbuf[0] = vv;
    }
    __syncthreads();
    v = sbuf[0];
    __syncthreads();
    return v;
}
__device__ __forceinline__ float block_reduce_sum(float v, float* sbuf) {
#pragma unroll
    for (int o = 16; o; o >>= 1) v += __shfl_xor_sync(0xffffffffu, v, o);
    int lane = threadIdx.x & 31, w = threadIdx.x >> 5;
    if (lane == 0) sbuf[w] = v;
    __syncthreads();
    if (threadIdx.x < 32) {
        float vv = (threadIdx.x < 8) ? sbuf[threadIdx.x] : 0.f;
#pragma unroll
        for (int o = 4; o; o >>= 1) vv += __shfl_xor_sync(0xffffffffu, vv, o);
        if (threadIdx.x == 0) sbuf[0] = vv;
    }
    __syncthreads();
    v = sbuf[0];
    __syncthreads();
    return v;
}

// softmax/interp/shift/sharpen from per-element score sc[] -> w_hd
__device__ __forceinline__ void fin_core(float* sc, int hd, int b, float gate,
                                         float s0, float s1, float s2, float gamma,
                                         const float* pw, float* sbuf, float* swg) {
    int tid = threadIdx.x;
    float lmax = -3.4e38f;
#pragma unroll
    for (int t = 0; t < 16; ++t) lmax = fmaxf(lmax, sc[t]);
    float bmax = block_reduce_max(lmax, sbuf);
    float lsum = 0.f;
#pragma unroll
    for (int t = 0; t < 16; ++t) { float e = __expf(sc[t] - bmax); sc[t] = e; lsum += e; }
    float bsum = block_reduce_sum(lsum, sbuf);
    float inv = 1.f / bsum;
#pragma unroll
    for (int t = 0; t < 16; ++t) {
        int idx = tid + t * 256;
        swg[idx] = gate * sc[t] * inv + (1.f - gate) * pw[idx];
    }
    __syncthreads();
    float wp[16];
    float lps = 0.f;
#pragma unroll
    for (int t = 0; t < 16; ++t) {
        int idx = tid + t * 256;
        float ws = s0 * swg[(idx + N_ - 1) & (N_ - 1)] + s1 * swg[idx]
                 + s2 * swg[(idx + 1) & (N_ - 1)];
        float p = __powf(ws, gamma);
        wp[t] = p; lps += p;
    }
    float psum = block_reduce_sum(lps, sbuf);
    float invp = 1.f / (psum + EPSV);
    float* wout = g_w + (size_t)hd * RBN + (size_t)b * N_;
#pragma unroll
    for (int t = 0; t < 16; ++t) {
        int idx = tid + t * 256;
        wout[idx] = wp[t] * invp;
    }
}

// fin for heads 0-3 after pass A: 0,1 direct; 2,3 assembled from pass-A reductions
__global__ void finA_kernel(const float* __restrict__ prevW) {
    __shared__ float swg[N_];
    __shared__ float sbuf[8];
    int b = blockIdx.x;
    int hd = blockIdx.y;          // 0..3
    int tid = threadIdx.x;
    int hb = hd * B_ + b;
    float knorm = g_knorm[hb], beta = g_beta[hb], gate = g_gate[hb], gamma = g_gamma[hb];
    float s0 = g_s[hb * 3 + 0], s1 = g_s[hb * 3 + 1], s2 = g_s[hb * 3 + 2];
    const float* pw = prevW + ((size_t)hd * B_ + b) * N_;
    const size_t base = (size_t)b * N_;
    float sc[16];
    if (hd < 2) {
        const float* dot = hd ? RED(1) : RED(0);
        const float* nrm = RED(2);
#pragma unroll
        for (int t = 0; t < 16; ++t) {
            int idx = tid + t * 256;
            float d = dot[base + idx];
            float nr = nrm[base + idx];
            sc[t] = beta * d / (sqrtf(nr) * knorm + EPSV);
        }
    } else {
        int hh = hd - 2;
        float Ax = hh ? g_A3[b] : g_A2[b];
        float Aaa = g_Aaa[b];
        const float* ua = hh ? RED(5) : RED(3);
        const float* ub = hh ? RED(6) : RED(4);
        const float* nrm = RED(2);
        const float* r5 = RED(7); const float* r6 = RED(8);
        const float* r7 = RED(9); const float* r8 = RED(10);
        const float* wp1 = g_w + 1 * RBN + base;
#pragma unroll
        for (int t = 0; t < 16; ++t) {
            int idx = tid + t * 256;
            float w1 = wp1[idx];
            float d = ua[base + idx] + w1 * (Ax - ub[base + idx]);
            float nrm1 = nrm[base + idx]
                       + 2.f * w1 * (r5[base + idx] - r6[base + idx])
                       + w1 * w1 * (Aaa - 2.f * r7[base + idx] + r8[base + idx]);
            nrm1 = fmaxf(nrm1, 0.f);
            sc[t] = beta * d / (sqrtf(nrm1) * knorm + EPSV);
        }
    }
    fin_core(sc, hd, b, gate, s0, s1, s2, gamma, pw, sbuf, swg);
}

__global__ void fin_kernel(int head0, const float* __restrict__ prevW) {
    __shared__ float swg[N_];
    __shared__ float sbuf[8];
    int b = blockIdx.x;
    int hh = blockIdx.y;
    int hd = head0 + hh;
    int tid = threadIdx.x;
    const float* dot = hh ? RED(1) : RED(0);
    const float* nrm = RED(2);
    int hb = hd * B_ + b;
    float knorm = g_knorm[hb], beta = g_beta[hb], gate = g_gate[hb], gamma = g_gamma[hb];
    float s0 = g_s[hb * 3 + 0], s1 = g_s[hb * 3 + 1], s2 = g_s[hb * 3 + 2];
    const float* pw = prevW + ((size_t)hd * B_ + b) * N_;
    const size_t base = (size_t)b * N_;
    float sc[16];
#pragma unroll
    for (int t = 0; t < 16; ++t) {
        int idx = tid + t * 256;
        float d = dot[base + idx];
        float nr = nrm[base + idx];
        sc[t] = beta * d / (sqrtf(nr) * knorm + EPSV);
    }
    fin_core(sc, hd, b, gate, s0, s1, s2, gamma, pw, sbuf, swg);
}

// fin for head 6: assemble dot6/nrm3 from pass-D reductions + w5; also T[b] = sum w6 w5
__global__ void fin6_kernel(const float* __restrict__ prevW) {
    __shared__ float swg[N_];
    __shared__ float sbuf[8];
    int b = blockIdx.x;
    int tid = threadIdx.x;
    const int hd = 6;
    int hb = hd * B_ + b;
    float knorm = g_knorm[hb], beta = g_beta[hb], gate = g_gate[hb], gamma = g_gamma[hb];
    float s0 = g_s[hb * 3 + 0], s1 = g_s[hb * 3 + 1], s2 = g_s[hb * 3 + 2];
    float ak = g_ak[b], aa = g_aa[b];
    const float* pw = prevW + ((size_t)hd * B_ + b) * N_;
    const float* wp5 = g_w + 5 * RBN + (size_t)b * N_;
    const size_t base = (size_t)b * N_;
    const float* d6ap = RED(0); const float* d6bp = RED(1);
    const float* q0p = RED(2);  const float* q1p = RED(3);
    const float* q2p = RED(4);  const float* p1p = RED(5);
    const float* p2p = RED(6);
    float sc[16];
#pragma unroll
    for (int t = 0; t < 16; ++t) {
        int idx = tid + t * 256;
        float w5 = wp5[idx];
        float d6 = d6ap[base + idx] + w5 * (ak - d6bp[base + idx]);
        float q0 = q0p[base + idx];
        float q1 = q1p[base + idx], q2 = q2p[base + idx];
        float p1 = p1p[base + idx], p2 = p2p[base + idx];
        float nrm3 = q0 + w5 * (-2.f * q1 + 2.f * p1) + w5 * w5 * (q2 - 2.f * p2 + aa);
        nrm3 = fmaxf(nrm3, 0.f);
        sc[t] = beta * d6 / (sqrtf(nrm3) * knorm + EPSV);
    }
    fin_core(sc, hd, b, gate, s0, s1, s2, gamma, pw, sbuf, swg);
    // T[b] = sum_n w6 w5
    const float* wout = g_w + 6 * RBN + base;
    float lt = 0.f;
#pragma unroll
    for (int t = 0; t < 16; ++t) {
        int idx = tid + t * 256;
        lt += wout[idx] * wp5[idx];
    }
    float T = block_reduce_sum(lt, sbuf);
    if (tid == 0) g_T[b] = T;
}

// ---------------- build state = [h | reads0 | reads2 | reads4 | reads6] ----------------
__global__ void build_state_kernel() {
    int b = blockIdx.x;
    for (int j = threadIdx.x; j < 768; j += blockDim.x) {
        float v;
        if (j < 512) v = g_h[(size_t)b * C_ + j];
        else {
            int ri = (j - 512) >> 6, m = (j - 512) & 63;
            if (ri < 3) {
                float s = 0.f;
                const float* rp = g_rpart + (size_t)ri * B_ * 16 * 64 + (size_t)b * 16 * 64 + m;
#pragma unroll
                for (int cc = 0; cc < 16; ++cc) s += rp[cc * 64];
                v = s;
            } else {
                float sa = 0.f, sb = 0.f;
                const float* rpa = g_rpart + (size_t)3 * B_ * 16 * 64 + (size_t)b * 16 * 64 + m;
                const float* rpb = g_rpart + (size_t)4 * B_ * 16 * 64 + (size_t)b * 16 * 64 + m;
#pragma unroll
                for (int cc = 0; cc < 16; ++cc) { sa += rpa[cc * 64]; sb += rpb[cc * 64]; }
                float e5 = g_e[((size_t)2 * B_ + b) * 64 + m];
                float a5 = g_a[((size_t)2 * B_ + b) * 64 + m];
                v = sa - e5 * sb + g_T[b] * a5;
            }
        }
        g_state[(size_t)b * 768 + j] = v;
    }
}

// ---------------- host ----------------
extern "C" void kernel_launch(void* const* d_in, const int* in_sizes, int n_in,
                              void* d_out, int out_size) {
    const float* in_data      = (const float*)d_in[0];
    const float* memory       = (const float*)d_in[1];
    const float* h0           = (const float*)d_in[2];
    const float* c0           = (const float*)d_in[3];
    const float* prev_weights = (const float*)d_in[4];
    const float* prev_reads   = (const float*)d_in[5];
    const float* W_ih         = (const float*)d_in[6];
    const float* b_ih         = (const float*)d_in[7];
    const float* W_hh         = (const float*)d_in[8];
    const float* b_hh         = (const float*)d_in[9];
    const float* W_out        = (const float*)d_in[10];
    const float* b_out        = (const float*)d_in[11];
    const float* W_addr       = (const float*)d_in[12];
    const float* b_addr       = (const float*)d_in[13];
    const float* W_ea         = (const float*)d_in[14];
    const float* b_ea         = (const float*)d_in[15];
    float* outp = (float*)d_out;

    // controller (split-K GEMMs)
    build_x_kernel<<<(B_ * 320 + 255) / 256, 256>>>(in_data, prev_reads);
    gates_gemm_kernel<<<dim3(2048 / 64, B_ / 64, 4), 256>>>(h0, W_ih, W_hh);
    lstm_kernel<<<(B_ * C_ + 255) / 256, 256>>>(c0, b_ih, b_hh);

    // head parameters (trimmed N=874: addr heads 0-6, ea heads 0-2; split-K 16)
    headpe_gemm_kernel<<<dim3((PEN + 63) / 64, B_ / 64, 16), 256>>>(W_addr, W_ea);
    head_act_kernel<<<B_, 256>>>(b_addr, b_ea);

    passA_kernel<<<NPASSBLK, 256>>>(memory);
    finA_kernel<<<dim3(B_, 4), 256>>>(prev_weights);       // heads 0-3
    passC_kernel<<<NPASSBLK, 256>>>(memory);
    fin_kernel<<<dim3(B_, 2), 256>>>(4, prev_weights);     // heads 4,5 (direct on m2)
    passD_kernel<<<NPASSBLK, 256>>>();
    fin6_kernel<<<B_, 256>>>(prev_weights);                // head 6 (assembled)
    passE_kernel<<<NPASSBLK, 256>>>();

    // output
    build_state_kernel<<<B_, 256>>>();
    out_gemm_kernel<<<dim3(1, B_ / 32, 4), 256>>>(W_out);
    out_fin_kernel<<<(B_ * 64 + 255) / 256, 256>>>(b_out, outp);
}

// round 15
// speedup vs baseline: 1.0618x; 1.0021x over previous
#include <cuda_runtime.h>
#include <cstdint>

#define B_  256
#define N_  4096
#define M_  64
#define C_  512
#define EPSV 1e-8f
#define NPASSBLK 296
#define NPAIRS   4096
#define RBN ((size_t)B_ * N_)
#define PEN 874
#define PE1 490
#define PEB ((size_t)B_ * PEN)
#define GTB ((size_t)B_ * 2048)
#define OTB ((size_t)B_ * 64)

// ---------------- packed f32x2 helpers (sm_103a FFMA2) ----------------
struct px2 { unsigned long long u; };
__device__ __forceinline__ px2 pk(float x, float y) {
    px2 r; asm("mov.b64 %0,{%1,%2};" : "=l"(r.u) : "f"(x), "f"(y)); return r;
}
__device__ __forceinline__ float2 up(px2 a) {
    float2 f; asm("mov.b64 {%0,%1},%2;" : "=f"(f.x), "=f"(f.y) : "l"(a.u)); return f;
}
__device__ __forceinline__ px2 fma2(px2 a, px2 b, px2 c) {
    px2 r; asm("fma.rn.f32x2 %0,%1,%2,%3;" : "=l"(r.u) : "l"(a.u), "l"(b.u), "l"(c.u)); return r;
}

// ---------------- device scratch ----------------
__device__ __align__(16) float g_mem[(size_t)B_ * N_ * M_];      // v2 working memory (written once, pass C)
__device__ __align__(16) float g_x[B_ * 320];
__device__ __align__(16) float g_gates4[4 * GTB];
__device__ __align__(16) float g_c[B_ * C_];
__device__ __align__(16) float g_h[B_ * C_];
__device__ __align__(16) float g_pe16[16 * PEB];
__device__ __align__(16) float g_out4[4 * OTB];
__device__ __align__(16) float g_k[7 * B_ * M_];
__device__ float g_knorm[7 * B_];
__device__ float g_beta[7 * B_];
__device__ float g_gate[7 * B_];
__device__ float g_s[7 * B_ * 3];
__device__ float g_gamma[7 * B_];
__device__ __align__(16) float g_e[3 * B_ * M_];
__device__ __align__(16) float g_a[3 * B_ * M_];
__device__ __align__(16) float g_red[11 * RBN];                  // reduction slots
__device__ __align__(16) float g_w[7 * RBN];                     // per-head weights, slot = head index
__device__ __align__(16) float g_rpart[5 * B_ * 16 * M_];        // colsum partials: reads0,2,4, Sa, Sb
__device__ float g_ak[B_];    // a5 . k6
__device__ float g_aa[B_];    // |a5|^2
__device__ float g_A2[B_];    // a1 . k2
__device__ float g_A3[B_];    // a1 . k3
__device__ float g_Aaa[B_];   // |a1|^2
__device__ float g_T[B_];     // sum_n w6 w5
__device__ __align__(16) float g_state[B_ * 768];

#define RED(i) (g_red + (size_t)(i) * RBN)

// ---------------- helpers ----------------
__device__ __forceinline__ float sigf(float x) { return 1.f / (1.f + expf(-x)); }
__device__ __forceinline__ float softplusf(float x) { return x > 20.f ? x : log1pf(expf(x)); }

// ---------------- build x = [in_data | prev_reads 0..3] ----------------
__global__ void build_x_kernel(const float* __restrict__ in_data,
                               const float* __restrict__ prev_reads) {
    int idx = blockIdx.x * blockDim.x + threadIdx.x;
    if (idx >= B_ * 320) return;
    int b = idx / 320, j = idx % 320;
    float v;
    if (j < 64) v = in_data[b * 64 + j];
    else { int i = (j - 64) >> 6, m = (j - 64) & 63; v = prev_reads[((size_t)i * B_ + b) * 64 + m]; }
    g_x[idx] = v;
}

// gates GEMM, 64x64 tile / 4x4 microtile, split-K 4: partials -> g_gates4[z]
__global__ void gates_gemm_kernel(const float* __restrict__ h0,
                                  const float* __restrict__ Wih,
                                  const float* __restrict__ Whh) {
    __shared__ __align__(16) float As[16][64];
    __shared__ __align__(16) float Bs[16][64];
    int tid = threadIdx.x;
    int z = blockIdx.z;
    const float* A = (z < 2) ? g_x : h0;
    const float* Bw = (z < 2) ? Wih : Whh;
    int K = (z < 2) ? 320 : 512;
    int kbeg = (z == 0) ? 0 : (z == 1) ? 160 : (z == 2) ? 0 : 256;
    int kend = (z == 0) ? 160 : (z == 1) ? 320 : (z == 2) ? 256 : 512;
    int m0 = blockIdx.y * 64, n0 = blockIdx.x * 64;
    int l_r = tid >> 2, l_k = (tid & 3) * 4;
    int ty = tid >> 4, tx = tid & 15;
    float acc[4][4] = {};
    const float* ap = A + (size_t)(m0 + l_r) * K + l_k;
    const float* bp = Bw + (size_t)(n0 + l_r) * K + l_k;
    float4 av = *(const float4*)(ap + kbeg);
    float4 bv = *(const float4*)(bp + kbeg);
    for (int k0 = kbeg; k0 < kend; k0 += 16) {
        __syncthreads();
        As[l_k + 0][l_r] = av.x; As[l_k + 1][l_r] = av.y;
        As[l_k + 2][l_r] = av.z; As[l_k + 3][l_r] = av.w;
        Bs[l_k + 0][l_r] = bv.x; Bs[l_k + 1][l_r] = bv.y;
        Bs[l_k + 2][l_r] = bv.z; Bs[l_k + 3][l_r] = bv.w;
        if (k0 + 16 < kend) {
            av = *(const float4*)(ap + k0 + 16);
            bv = *(const float4*)(bp + k0 + 16);
        }
        __syncthreads();
#pragma unroll
        for (int kk = 0; kk < 16; kk++) {
            float4 a = *(const float4*)&As[kk][ty << 2];
            float4 b = *(const float4*)&Bs[kk][tx << 2];
            acc[0][0] += a.x * b.x; acc[0][1] += a.x * b.y; acc[0][2] += a.x * b.z; acc[0][3] += a.x * b.w;
            acc[1][0] += a.y * b.x; acc[1][1] += a.y * b.y; acc[1][2] += a.y * b.z; acc[1][3] += a.y * b.w;
            acc[2][0] += a.z * b.x; acc[2][1] += a.z * b.y; acc[2][2] += a.z * b.z; acc[2][3] += a.z * b.w;
            acc[3][0] += a.w * b.x; acc[3][1] += a.w * b.y; acc[3][2] += a.w * b.z; acc[3][3] += a.w * b.w;
        }
    }
    float* outp = g_gates4 + (size_t)z * GTB;
#pragma unroll
    for (int i = 0; i < 4; i++) {
        int m = m0 + (ty << 2) + i;
#pragma unroll
        for (int j = 0; j < 4; j++) {
            int n = n0 + (tx << 2) + j;
            outp[(size_t)m * 2048 + n] = acc[i][j];
        }
    }
}

// head-param GEMM, trimmed N=874, 64x64 tile / 4x4 microtile, split-K 16 x 32
__global__ void headpe_gemm_kernel(const float* __restrict__ Wa,
                                   const float* __restrict__ We) {
    __shared__ __align__(16) float As[16][64];
    __shared__ __align__(16) float Bs[16][64];
    const int K = 512;
    int tid = threadIdx.x;
    int z = blockIdx.z;
    int kbeg = z * 32, kend = kbeg + 32;
    int m0 = blockIdx.y * 64, n0 = blockIdx.x * 64;
    int l_r = tid >> 2, l_k = (tid & 3) * 4;
    int ty = tid >> 4, tx = tid & 15;
    int brow = n0 + l_r;
    const float* browp = (brow < PE1) ? (Wa + (size_t)brow * K)
                                      : (We + (size_t)(brow - PE1) * K);
    bool bok = (brow < PEN);
    const float* ap = g_c + (size_t)(m0 + l_r) * K + l_k;
    float4 av = *(const float4*)(ap + kbeg);
    float4 bv = bok ? *(const float4*)(browp + l_k + kbeg) : make_float4(0.f, 0.f, 0.f, 0.f);
    float acc[4][4] = {};
    for (int k0 = kbeg; k0 < kend; k0 += 16) {
        __syncthreads();
        As[l_k + 0][l_r] = av.x; As[l_k + 1][l_r] = av.y;
        As[l_k + 2][l_r] = av.z; As[l_k + 3][l_r] = av.w;
        Bs[l_k + 0][l_r] = bv.x; Bs[l_k + 1][l_r] = bv.y;
        Bs[l_k + 2][l_r] = bv.z; Bs[l_k + 3][l_r] = bv.w;
        if (k0 + 16 < kend) {
            av = *(const float4*)(ap + k0 + 16);
            bv = bok ? *(const float4*)(browp + l_k + k0 + 16) : make_float4(0.f, 0.f, 0.f, 0.f);
        }
        __syncthreads();
#pragma unroll
        for (int kk = 0; kk < 16; kk++) {
            float4 a = *(const float4*)&As[kk][ty << 2];
            float4 b = *(const float4*)&Bs[kk][tx << 2];
            acc[0][0] += a.x * b.x; acc[0][1] += a.x * b.y; acc[0][2] += a.x * b.z; acc[0][3] += a.x * b.w;
            acc[1][0] += a.y * b.x; acc[1][1] += a.y * b.y; acc[1][2] += a.y * b.z; acc[1][3] += a.y * b.w;
            acc[2][0] += a.z * b.x; acc[2][1] += a.z * b.y; acc[2][2] += a.z * b.z; acc[2][3] += a.z * b.w;
            acc[3][0] += a.w * b.x; acc[3][1] += a.w * b.y; acc[3][2] += a.w * b.z; acc[3][3] += a.w * b.w;
        }
    }
    float* outp = g_pe16 + (size_t)z * PEB;
#pragma unroll
    for (int i = 0; i < 4; i++) {
        int m = m0 + (ty << 2) + i;
#pragma unroll
        for (int j = 0; j < 4; j++) {
            int n = n0 + (tx << 2) + j;
            if (n < PEN) outp[(size_t)m * PEN + n] = acc[i][j];
        }
    }
}

// output GEMM, split-K 4 x 192: partials -> g_out4[z]   (N=64, K=768)
__global__ void out_gemm_kernel(const float* __restrict__ Wo) {
    __shared__ __align__(16) float As[16][32];
    __shared__ __align__(16) float Bs[16][64];
    const int NN = 64, K = 768;
    int tid = threadIdx.x;
    int z = blockIdx.z;
    int kbeg = z * 192, kend = kbeg + 192;
    int m0 = blockIdx.y * 32, n0 = 0;
    int la_r = tid >> 3, la_k = (tid & 7) * 2;
    int lb_r = tid >> 2, lb_k = (tid & 3) * 4;
    int ty = tid >> 4, tx = tid & 15;
    const float* ap = g_state + (size_t)(m0 + la_r) * K + la_k;
    const float* bp = Wo + (size_t)(n0 + lb_r) * K + lb_k;
    float2 av = *(const float2*)(ap + kbeg);
    float4 bv = *(const float4*)(bp + kbeg);
    float acc[2][4] = {};
    for (int k0 = kbeg; k0 < kend; k0 += 16) {
        __syncthreads();
        As[la_k][la_r] = av.x; As[la_k + 1][la_r] = av.y;
        Bs[lb_k + 0][lb_r] = bv.x; Bs[lb_k + 1][lb_r] = bv.y;
        Bs[lb_k + 2][lb_r] = bv.z; Bs[lb_k + 3][lb_r] = bv.w;
        if (k0 + 16 < kend) {
            av = *(const float2*)(ap + k0 + 16);
            bv = *(const float4*)(bp + k0 + 16);
        }
        __syncthreads();
#pragma unroll
        for (int kk = 0; kk < 16; kk++) {
            float2 a = *(const float2*)&As[kk][ty << 1];
            float4 b = *(const float4*)&Bs[kk][tx << 2];
            acc[0][0] += a.x * b.x; acc[0][1] += a.x * b.y; acc[0][2] += a.x * b.z; acc[0][3] += a.x * b.w;
            acc[1][0] += a.y * b.x; acc[1][1] += a.y * b.y; acc[1][2] += a.y * b.z; acc[1][3] += a.y * b.w;
        }
    }
    float* outp = g_out4 + (size_t)z * OTB;
#pragma unroll
    for (int i = 0; i < 2; i++) {
        int m = m0 + (ty << 1) + i;
#pragma unroll
        for (int j = 0; j < 4; j++) {
            int n = n0 + (tx << 2) + j;
            outp[(size_t)m * NN + n] = acc[i][j];
        }
    }
}

// out finalize: sum split-K partials + bias, sigmoid
__global__ void out_fin_kernel(const float* __restrict__ bo, float* __restrict__ C) {
    int idx = blockIdx.x * 256 + threadIdx.x;
    if (idx >= B_ * 64) return;
    int n = idx & 63;
    float s = g_out4[idx] + g_out4[OTB + idx] + g_out4[2 * OTB + idx] + g_out4[3 * OTB + idx];
    C[idx] = sigf(s + bo[n]);
}

// ---------------- LSTM pointwise (sums gates split-K partials + biases) ----------------
__global__ void lstm_kernel(const float* __restrict__ c0,
                            const float* __restrict__ bih, const float* __restrict__ bhh) {
    int idx = blockIdx.x * blockDim.x + threadIdx.x;
    if (idx >= B_ * C_) return;
    int b = idx / C_, j = idx % C_;
    size_t base = (size_t)b * 2048;
    float g4[4];
#pragma unroll
    for (int gi = 0; gi < 4; ++gi) {
        size_t o = base + gi * 512 + j;
        g4[gi] = g_gates4[o] + g_gates4[GTB + o] + g_gates4[2 * GTB + o] + g_gates4[3 * GTB + o]
               + bih[gi * 512 + j] + bhh[gi * 512 + j];
    }
    float c = sigf(g4[1]) * c0[idx] + sigf(g4[0]) * tanhf(g4[2]);
    g_c[idx] = c;
    g_h[idx] = sigf(g4[3]) * tanhf(c);
}

// ---------------- head activations (stage pe = sum 16 partials + bias into smem) ----------------
// trimmed layout: [0,490): addr heads 0..6 (70 each); [490,874): ea heads 0..2 (128 each)
__global__ void head_act_kernel(const float* __restrict__ ba, const float* __restrict__ be) {
    __shared__ float spe[PEN];
    int b = blockIdx.x;
    int tid = threadIdx.x;
    for (int j = tid; j < PEN; j += 256) {
        size_t o = (size_t)b * PEN + j;
        float bias = (j < PE1) ? ba[j] : be[j - PE1];
        float s = 0.f;
#pragma unroll
        for (int zz = 0; zz < 16; ++zz) s += g_pe16[(size_t)zz * PEB + o];
        spe[j] = s + bias;
    }
    __syncthreads();
    int wid = tid >> 5, lane = tid & 31;
    if (wid < 7) {
        int hd = wid;
        const float* p = spe + hd * 70;
        float ssq = 0.f;
        for (int j = lane; j < 64; j += 32) {
            float kv = tanhf(p[j]);
            g_k[((size_t)hd * B_ + b) * 64 + j] = kv;
            ssq += kv * kv;
        }
#pragma unroll
        for (int o = 16; o; o >>= 1) ssq += __shfl_xor_sync(0xffffffffu, ssq, o);
        if (lane == 0) {
            int hb = hd * B_ + b;
            g_knorm[hb] = sqrtf(ssq);
            g_beta[hb] = softplusf(p[64]);
            g_gate[hb] = sigf(p[65]);
            float s0 = p[66], s1 = p[67], s2 = p[68];
            float mx = fmaxf(s0, fmaxf(s1, s2));
            float e0 = expf(s0 - mx), e1 = expf(s1 - mx), e2 = expf(s2 - mx);
            float inv = 1.f / (e0 + e1 + e2);
            g_s[hb * 3 + 0] = e0 * inv; g_s[hb * 3 + 1] = e1 * inv; g_s[hb * 3 + 2] = e2 * inv;
            g_gamma[hb] = 1.f + softplusf(p[69]);
        }
    } else {
        for (int wh = 0; wh < 3; ++wh) {
            const float* ea = spe + PE1 + wh * 128;
            for (int j = lane; j < 64; j += 32) {
                g_e[((size_t)wh * B_ + b) * 64 + j] = sigf(ea[j]);
                g_a[((size_t)wh * B_ + b) * 64 + j] = tanhf(ea[64 + j]);
            }
        }
        const float* ea2 = spe + PE1 + 2 * 128;
        const float* ea0 = spe + PE1 + 0 * 128;
        const float* p6  = spe + 6 * 70;
        const float* p2  = spe + 2 * 70;
        const float* p3  = spe + 3 * 70;
        float pak = 0.f, paa = 0.f, pa2 = 0.f, pa3 = 0.f, p11 = 0.f;
        for (int j = lane; j < 64; j += 32) {
            float a5v = tanhf(ea2[64 + j]);
            float k6v = tanhf(p6[j]);
            float a1v = tanhf(ea0[64 + j]);
            float k2v = tanhf(p2[j]);
            float k3v = tanhf(p3[j]);
            pak += a5v * k6v; paa += a5v * a5v;
            pa2 += a1v * k2v; pa3 += a1v * k3v; p11 += a1v * a1v;
        }
#pragma unroll
        for (int o = 16; o; o >>= 1) {
            pak += __shfl_xor_sync(0xffffffffu, pak, o);
            paa += __shfl_xor_sync(0xffffffffu, paa, o);
            pa2 += __shfl_xor_sync(0xffffffffu, pa2, o);
            pa3 += __shfl_xor_sync(0xffffffffu, pa3, o);
            p11 += __shfl_xor_sync(0xffffffffu, p11, o);
        }
        if (lane == 0) {
            g_ak[b] = pak; g_aa[b] = paa;
            g_A2[b] = pa2; g_A3[b] = pa3; g_Aaa[b] = p11;
        }
    }
}

// =================== persistent grid-stride memory passes ===================
#define PASS_HEAD()                                                         \
    int tid = threadIdx.x, lane = tid & 31, warp = tid >> 5;                \
    int c = lane & 7, rg = lane >> 3, col0 = c * 8;                         \
    int p0 = (NPAIRS * blockIdx.x) / NPASSBLK;                              \
    int p1 = (NPAIRS * (blockIdx.x + 1)) / NPASSBLK;                        \
    int Lend = p1 * 8;

#define LOADOP(dst, baseptr) {                                              \
    const float4* _q = (const float4*)((baseptr) + col0);                   \
    float4 _u0 = __ldg(_q), _u1 = __ldg(_q + 1);                            \
    dst[0] = pk(_u0.x, _u0.y); dst[1] = pk(_u0.z, _u0.w);                   \
    dst[2] = pk(_u1.x, _u1.y); dst[3] = pk(_u1.z, _u1.w); }
#define LOADOPN(dst, baseptr) {                                             \
    const float4* _q = (const float4*)((baseptr) + col0);                   \
    float4 _u0 = __ldg(_q), _u1 = __ldg(_q + 1);                            \
    dst[0] = pk(-_u0.x, -_u0.y); dst[1] = pk(-_u0.z, -_u0.w);               \
    dst[2] = pk(-_u1.x, -_u1.y); dst[3] = pk(-_u1.z, -_u1.w); }

__device__ __forceinline__ void reads_epilogue(px2* acc, float (*sred)[64],
                                               int lane, int warp, int c, int tid,
                                               int pair, int slot) {
    float va[8];
#pragma unroll
    for (int i = 0; i < 4; ++i) { float2 f = up(acc[i]); va[2 * i] = f.x; va[2 * i + 1] = f.y; }
#pragma unroll
    for (int t = 0; t < 8; ++t) {
        va[t] += __shfl_xor_sync(0xffffffffu, va[t], 8);
        va[t] += __shfl_xor_sync(0xffffffffu, va[t], 16);
    }
    if (lane < 8) {
#pragma unroll
        for (int t = 0; t < 8; ++t) sred[warp][c * 8 + t] = va[t];
    }
    __syncthreads();
    if (tid < 64) {
        float s = 0.f;
#pragma unroll
        for (int wv = 0; wv < 8; ++wv) s += sred[wv][tid];
        g_rpart[(size_t)slot * B_ * 16 * 64 + (size_t)pair * 64 + tid] = s;
    }
    __syncthreads();
}

// ---- Pass A: 11 reductions on mem0 (heads 0-3 material), reduce-scatter ----
// slots: 0:dot0 1:dot1 2:nrm0 3:u2a 4:u2b 5:u3a 6:u3b 7:v1a 8:v2a 9:v3a 10:v4a
__global__ __launch_bounds__(256, 2) void passA_kernel(const float* __restrict__ mem0) {
    PASS_HEAD();
    float4 bufA[4], bufB[4];
#define LD_A(L) { size_t n = (size_t)(L) * 32 + warp * 4 + rg;              \
        const float4* p = (const float4*)(mem0 + n * 64 + col0);            \
        bufA[(L) & 3] = __ldcs(p); bufB[(L) & 3] = __ldcs(p + 1); }
    LD_A(p0 * 8); LD_A(p0 * 8 + 1); LD_A(p0 * 8 + 2);
    px2 k0[4], k1[4], k2[4], k3[4], e1[4], a1[4];
    int bcur = -1;
    px2 pz = pk(0.f, 0.f);
    bool oddc = (c & 1), bit1 = (c & 2);
    int sbase = (c == 0) ? 0 : (c == 1) ? 6 : (c == 2) ? 3 : 9;
    for (int p = p0; p < p1; ++p) {
        int b = p >> 4;
        if (b != bcur) {
            bcur = b;
            LOADOP(k0, g_k + ((size_t)0 * B_ + b) * 64);
            LOADOP(k1, g_k + ((size_t)1 * B_ + b) * 64);
            LOADOP(k2, g_k + ((size_t)2 * B_ + b) * 64);
            LOADOP(k3, g_k + ((size_t)3 * B_ + b) * 64);
            LOADOP(e1, g_e + ((size_t)0 * B_ + b) * 64);
            LOADOP(a1, g_a + ((size_t)0 * B_ + b) * 64);
        }
#pragma unroll
        for (int it = 0; it < 8; ++it) {
            int L = p * 8 + it;
            if (L + 3 < Lend) LD_A(L + 3);
            size_t n = (size_t)L * 32 + warp * 4 + rg;
            float4 A = bufA[it & 3], Bv = bufB[it & 3];
            px2 v[4] = { pk(A.x, A.y), pk(A.z, A.w), pk(Bv.x, Bv.y), pk(Bv.z, Bv.w) };
            px2 d0 = pz, d1 = pz, nr = pz, u2a = pz, u2b = pz, u3a = pz, u3b = pz;
            px2 v1a = pz, v2a = pz, v3a = pz, v4a = pz;
#pragma unroll
            for (int i = 0; i < 4; ++i) {
                px2 ve = fma2(v[i], e1[i], pz);
                d0  = fma2(v[i], k0[i], d0);
                d1  = fma2(v[i], k1[i], d1);
                nr  = fma2(v[i], v[i], nr);
                u2a = fma2(v[i], k2[i], u2a);
                u3a = fma2(v[i], k3[i], u3a);
                u2b = fma2(ve, k2[i], u2b);
                u3b = fma2(ve, k3[i], u3b);
                v1a = fma2(v[i], a1[i], v1a);
                v3a = fma2(ve, a1[i], v3a);
                v2a = fma2(ve, v[i], v2a);
                v4a = fma2(ve, ve, v4a);
            }
            float s[11]; float2 f;
            f = up(d0);  s[0] = f.x + f.y;
            f = up(d1);  s[1] = f.x + f.y;
            f = up(nr);  s[2] = f.x + f.y;
            f = up(u2a); s[3] = f.x + f.y;
            f = up(u2b); s[4] = f.x + f.y;
            f = up(u3a); s[5] = f.x + f.y;
            f = up(u3b); s[6] = f.x + f.y;
            f = up(v1a); s[7] = f.x + f.y;
            f = up(v2a); s[8] = f.x + f.y;
            f = up(v3a); s[9] = f.x + f.y;
            f = up(v4a); s[10] = f.x + f.y;
            // reduce-scatter over 8 lanes (c bits)
#pragma unroll
            for (int t = 0; t < 11; ++t) s[t] += __shfl_xor_sync(0xffffffffu, s[t], 1);
            float kk[6];
            kk[0] = oddc ? s[6]  : s[0];
            kk[1] = oddc ? s[7]  : s[1];
            kk[2] = oddc ? s[8]  : s[2];
            kk[3] = oddc ? s[9]  : s[3];
            kk[4] = oddc ? s[10] : s[4];
            kk[5] = oddc ? s[10] : s[5];
#pragma unroll
            for (int t = 0; t < 6; ++t) kk[t] += __shfl_xor_sync(0xffffffffu, kk[t], 2);
            float m0v = bit1 ? kk[3] : kk[0];
            float m1v = bit1 ? kk[4] : kk[1];
            float m2v = bit1 ? kk[5] : kk[2];
            m0v += __shfl_xor_sync(0xffffffffu, m0v, 4);
            m1v += __shfl_xor_sync(0xffffffffu, m1v, 4);
            m2v += __shfl_xor_sync(0xffffffffu, m2v, 4);
            // classes: c0:{0,1,2} c1:{6,7,8} c2:{3,4,5} c3:{9,10}
            if (c < 4) {
                g_red[(size_t)sbase * RBN + n] = m0v;
                g_red[(size_t)(sbase + 1) * RBN + n] = m1v;
                if (c < 3) g_red[(size_t)(sbase + 2) * RBN + n] = m2v;
            }
        }
    }
}

// ---- Pass C: reads0 (w0,m0), m1 regs, reads2 (w2,m1), update -> write v2, dot4, dot5, nrm2 ----
// slots: 0:dot4 1:dot5 2:nrm2
__global__ __launch_bounds__(256, 2) void passC_kernel(const float* __restrict__ mem0) {
    __shared__ float sred[8][64];
    PASS_HEAD();
    const float* wp0 = g_w + 0 * RBN;
    const float* wp1 = g_w + 1 * RBN;
    const float* wp2 = g_w + 2 * RBN;
    const float* wp3 = g_w + 3 * RBN;
    float4 bufA[4], bufB[4];
#define LD_C(L) { size_t n = (size_t)(L) * 32 + warp * 4 + rg;              \
        const float4* p = (const float4*)(mem0 + n * 64 + col0);            \
        bufA[(L) & 3] = __ldcs(p); bufB[(L) & 3] = __ldcs(p + 1); }
    LD_C(p0 * 8); LD_C(p0 * 8 + 1);
    px2 k4[4], k5[4], ne1[4], a1[4], ne3[4], a3[4];
    int bcur = -1;
    px2 pz = pk(0.f, 0.f);
    for (int p = p0; p < p1; ++p) {
        int b = p >> 4;
        if (b != bcur) {
            bcur = b;
            LOADOP(k4, g_k + ((size_t)4 * B_ + b) * 64);
            LOADOP(k5, g_k + ((size_t)5 * B_ + b) * 64);
            LOADOPN(ne1, g_e + ((size_t)0 * B_ + b) * 64);
            LOADOP(a1, g_a + ((size_t)0 * B_ + b) * 64);
            LOADOPN(ne3, g_e + ((size_t)1 * B_ + b) * 64);
            LOADOP(a3, g_a + ((size_t)1 * B_ + b) * 64);
        }
        px2 acc0[4] = { pz, pz, pz, pz };
        px2 acc2[4] = { pz, pz, pz, pz };
#pragma unroll
        for (int it = 0; it < 8; ++it) {
            int L = p * 8 + it;
            if (L + 2 < Lend) LD_C(L + 2);
            size_t n = (size_t)L * 32 + warp * 4 + rg;
            float w0 = __ldg(wp0 + n), w1 = __ldg(wp1 + n);
            float w2 = __ldg(wp2 + n), w3 = __ldg(wp3 + n);
            float4 A = bufA[it & 3], Bv = bufB[it & 3];
            px2 v[4] = { pk(A.x, A.y), pk(A.z, A.w), pk(Bv.x, Bv.y), pk(Bv.z, Bv.w) };
            px2 w0p = pk(w0, w0), w1p = pk(w1, w1), w2p = pk(w2, w2), w3p = pk(w3, w3);
            px2 d4 = pz, d5 = pz, nr = pz;
#pragma unroll
            for (int i = 0; i < 4; ++i) {
                acc0[i] = fma2(w0p, v[i], acc0[i]);              // reads0 on m0
                px2 t = fma2(ne1[i], v[i], a1[i]);
                px2 m1 = fma2(w1p, t, v[i]);
                acc2[i] = fma2(w2p, m1, acc2[i]);                // reads2 on m1
                px2 t3 = fma2(ne3[i], m1, a3[i]);
                px2 m2 = fma2(w3p, t3, m1);
                v[i] = m2;
                d4 = fma2(m2, k4[i], d4);
                d5 = fma2(m2, k5[i], d5);
                nr = fma2(m2, m2, nr);
            }
            float* po = g_mem + n * 64 + col0;
            float2 f0 = up(v[0]), f1 = up(v[1]);
            __stcs((float4*)po, make_float4(f0.x, f0.y, f1.x, f1.y));
            float2 f2 = up(v[2]), f3 = up(v[3]);
            __stcs((float4*)po + 1, make_float4(f2.x, f2.y, f3.x, f3.y));
            float2 fd4 = up(d4), fd5 = up(d5), fn = up(nr);
            float s0 = fd4.x + fd4.y, s1 = fd5.x + fd5.y, sn = fn.x + fn.y;
#pragma unroll
            for (int o = 1; o <= 4; o <<= 1) {
                s0 += __shfl_xor_sync(0xffffffffu, s0, o);
                s1 += __shfl_xor_sync(0xffffffffu, s1, o);
                sn += __shfl_xor_sync(0xffffffffu, sn, o);
            }
            // lane-distributed store: lane c stores slot c (c<3)
            float outv = (c == 0) ? s0 : (c == 1) ? s1 : sn;
            if (c < 3) g_red[(size_t)c * RBN + n] = outv;
        }
        reads_epilogue(acc0, sred, lane, warp, c, tid, p, 0);
        reads_epilogue(acc2, sred, lane, warp, c, tid, p, 1);
    }
}

// ---- Pass D: reads4 + algebraic reductions for head 6 on v2 (NO memory write) ----
// values: 0:d6a 1:d6b 2:q1 3:q2 4:p1 5:p2 -> slots {0,1,3,4,5,6} (slot2 = nrm2 preserved)
__global__ __launch_bounds__(256, 2) void passD_kernel() {
    __shared__ float sred[8][64];
    PASS_HEAD();
    const float* wp4 = g_w + 4 * RBN;
    float4 bufA[4], bufB[4];
#define LD_D(L) { size_t n = (size_t)(L) * 32 + warp * 4 + rg;              \
        const float4* p = (const float4*)(g_mem + n * 64 + col0);           \
        bufA[(L) & 3] = __ldcs(p); bufB[(L) & 3] = __ldcs(p + 1); }
    LD_D(p0 * 8); LD_D(p0 * 8 + 1); LD_D(p0 * 8 + 2);
    px2 k6[4], ek[4], e5[4], es[4], a5[4], ea[4];
    int bcur = -1;
    px2 pz = pk(0.f, 0.f);
    bool oddc = (c & 1), bit1 = (c & 2);
    // classes: c0:{v0,v1}->slots{0,1}; c1:{v3,v4}->slots{4,5}; c2:{v2}->slot{3}; c3:{v5}->slot{6}
    int slotA = (c == 0) ? 0 : (c == 1) ? 4 : (c == 2) ? 3 : 6;
    int slotB = (c == 0) ? 1 : 5;
    for (int p = p0; p < p1; ++p) {
        int b = p >> 4;
        if (b != bcur) {
            bcur = b;
            float kk[8], ee[8], av[8];
            const float4* qk = (const float4*)(g_k + ((size_t)6 * B_ + b) * 64 + col0);
            const float4* qe = (const float4*)(g_e + ((size_t)2 * B_ + b) * 64 + col0);
            const float4* qa = (const float4*)(g_a + ((size_t)2 * B_ + b) * 64 + col0);
            *(float4*)&kk[0] = __ldg(qk); *(float4*)&kk[4] = __ldg(qk + 1);
            *(float4*)&ee[0] = __ldg(qe); *(float4*)&ee[4] = __ldg(qe + 1);
            *(float4*)&av[0] = __ldg(qa); *(float4*)&av[4] = __ldg(qa + 1);
#pragma unroll
            for (int i = 0; i < 4; ++i) {
                float k0v = kk[2*i], k1v = kk[2*i+1];
                float e0v = ee[2*i], e1v = ee[2*i+1];
                float a0v = av[2*i], a1v = av[2*i+1];
                k6[i] = pk(k0v, k1v);
                e5[i] = pk(e0v, e1v);
                ek[i] = pk(e0v * k0v, e1v * k1v);
                es[i] = pk(e0v * e0v, e1v * e1v);
                a5[i] = pk(a0v, a1v);
                ea[i] = pk(e0v * a0v, e1v * a1v);
            }
        }
        px2 acc[4] = { pz, pz, pz, pz };
#pragma unroll
        for (int it = 0; it < 8; ++it) {
            int L = p * 8 + it;
            if (L + 3 < Lend) LD_D(L + 3);
            size_t n = (size_t)L * 32 + warp * 4 + rg;
            float w4 = __ldg(wp4 + n);
            float4 A = bufA[it & 3], Bv = bufB[it & 3];
            px2 v[4] = { pk(A.x, A.y), pk(A.z, A.w), pk(Bv.x, Bv.y), pk(Bv.z, Bv.w) };
            px2 w4p = pk(w4, w4);
            px2 d6a = pz, d6b = pz, q1 = pz, q2 = pz, p1v = pz, p2v = pz;
#pragma unroll
            for (int i = 0; i < 4; ++i) {
                acc[i] = fma2(w4p, v[i], acc[i]);               // reads4 on m2
                px2 vsq = fma2(v[i], v[i], pz);
                d6a = fma2(v[i], k6[i], d6a);
                d6b = fma2(v[i], ek[i], d6b);
                q1  = fma2(vsq, e5[i], q1);
                q2  = fma2(vsq, es[i], q2);
                p1v = fma2(v[i], a5[i], p1v);
                p2v = fma2(v[i], ea[i], p2v);
            }
            float s[6]; float2 f;
            f = up(d6a); s[0] = f.x + f.y;
            f = up(d6b); s[1] = f.x + f.y;
            f = up(q1);  s[2] = f.x + f.y;
            f = up(q2);  s[3] = f.x + f.y;
            f = up(p1v); s[4] = f.x + f.y;
            f = up(p2v); s[5] = f.x + f.y;
#pragma unroll
            for (int t = 0; t < 6; ++t) s[t] += __shfl_xor_sync(0xffffffffu, s[t], 1);
            float kk0 = oddc ? s[3] : s[0];
            float kk1 = oddc ? s[4] : s[1];
            float kk2 = oddc ? s[5] : s[2];
            kk0 += __shfl_xor_sync(0xffffffffu, kk0, 2);
            kk1 += __shfl_xor_sync(0xffffffffu, kk1, 2);
            kk2 += __shfl_xor_sync(0xffffffffu, kk2, 2);
            float m0v = bit1 ? kk2 : kk0;
            float m1v = bit1 ? kk2 : kk1;   // m1v only valid for c<2 classes
            m0v += __shfl_xor_sync(0xffffffffu, m0v, 4);
            m1v += __shfl_xor_sync(0xffffffffu, m1v, 4);
            if (c < 4) g_red[(size_t)slotA * RBN + n] = m0v;
            if (c < 2) g_red[(size_t)slotB * RBN + n] = m1v;
        }
        reads_epilogue(acc, sred, lane, warp, c, tid, p, 2);
    }
}

// ---- Pass E: Sa = colsum(w6, v2), Sb = colsum(w6*w5, v2) ----
__global__ __launch_bounds__(256, 2) void passE_kernel() {
    __shared__ float sredA[8][64];
    __shared__ float sredB[8][64];
    PASS_HEAD();
    const float* wp5 = g_w + 5 * RBN;
    const float* wp6 = g_w + 6 * RBN;
    float4 bufA[4], bufB[4];
#define LD_E(L) { size_t n = (size_t)(L) * 32 + warp * 4 + rg;              \
        const float4* p = (const float4*)(g_mem + n * 64 + col0);           \
        bufA[(L) & 3] = __ldcs(p); bufB[(L) & 3] = __ldcs(p + 1); }
    LD_E(p0 * 8); LD_E(p0 * 8 + 1); LD_E(p0 * 8 + 2);
    for (int p = p0; p < p1; ++p) {
        px2 accA[4], accB[4];
#pragma unroll
        for (int i = 0; i < 4; ++i) { accA[i] = pk(0.f, 0.f); accB[i] = pk(0.f, 0.f); }
#pragma unroll
        for (int it = 0; it < 8; ++it) {
            int L = p * 8 + it;
            if (L + 3 < Lend) LD_E(L + 3);
            size_t n = (size_t)L * 32 + warp * 4 + rg;
            float w5 = __ldg(wp5 + n), w6 = __ldg(wp6 + n);
            float4 A = bufA[it & 3], Bv = bufB[it & 3];
            px2 v[4] = { pk(A.x, A.y), pk(A.z, A.w), pk(Bv.x, Bv.y), pk(Bv.z, Bv.w) };
            px2 w6p = pk(w6, w6), w65p = pk(w6 * w5, w6 * w5);
#pragma unroll
            for (int i = 0; i < 4; ++i) {
                accA[i] = fma2(w6p, v[i], accA[i]);
                accB[i] = fma2(w65p, v[i], accB[i]);
            }
        }
        reads_epilogue(accA, sredA, lane, warp, c, tid, p, 3);
        reads_epilogue(accB, sredB, lane, warp, c, tid, p, 4);
    }
}

// ---------------- finalize helpers ----------------
__device__ __forceinline__ float block_reduce_max(float v, float* sbuf) {
#pragma unroll
    for (int o = 16; o; o >>= 1) v = fmaxf(v, __shfl_xor_sync(0xffffffffu, v, o));
    int lane = threadIdx.x & 31, w = threadIdx.x >> 5;
    if (lane == 0) sbuf[w] = v;
    __syncthreads();
    if (threadIdx.x < 32) {
        float vv = (threadIdx.x < 8) ? sbuf[threadIdx.x] : -3.4e38f;
#pragma unroll
        for (int o = 4; o; o >>= 1) vv = fmaxf(vv, __shfl_xor_sync(0xffffffffu, vv, o));
        if (threadIdx.x == 0) sbuf[0] = vv;
    }
    __syncthreads();
    v = sbuf[0];
    __syncthreads();
    return v;
}
__device__ __forceinline__ float block_reduce_sum(float v, float* sbuf) {
#pragma unroll
    for (int o = 16; o; o >>= 1) v += __shfl_xor_sync(0xffffffffu, v, o);
    int lane = threadIdx.x & 31, w = threadIdx.x >> 5;
    if (lane == 0) sbuf[w] = v;
    __syncthreads();
    if (threadIdx.x < 32) {
        float vv = (threadIdx.x < 8) ? sbuf[threadIdx.x] : 0.f;
#pragma unroll
        for (int o = 4; o; o >>= 1) vv += __shfl_xor_sync(0xffffffffu, vv, o);
        if (threadIdx.x == 0) sbuf[0] = vv;
    }
    __syncthreads();
    v = sbuf[0];
    __syncthreads();
    return v;
}

// softmax/interp/shift/sharpen from per-element score sc[] -> w_hd
__device__ __forceinline__ void fin_core(float* sc, int hd, int b, float gate,
                                         float s0, float s1, float s2, float gamma,
                                         const float* pw, float* sbuf, float* swg) {
    int tid = threadIdx.x;
    float lmax = -3.4e38f;
#pragma unroll
    for (int t = 0; t < 16; ++t) lmax = fmaxf(lmax, sc[t]);
    float bmax = block_reduce_max(lmax, sbuf);
    float lsum = 0.f;
#pragma unroll
    for (int t = 0; t < 16; ++t) { float e = __expf(sc[t] - bmax); sc[t] = e; lsum += e; }
    float bsum = block_reduce_sum(lsum, sbuf);
    float inv = 1.f / bsum;
#pragma unroll
    for (int t = 0; t < 16; ++t) {
        int idx = tid + t * 256;
        swg[idx] = gate * sc[t] * inv + (1.f - gate) * pw[idx];
    }
    __syncthreads();
    float wp[16];
    float lps = 0.f;
#pragma unroll
    for (int t = 0; t < 16; ++t) {
        int idx = tid + t * 256;
        float ws = s0 * swg[(idx + N_ - 1) & (N_ - 1)] + s1 * swg[idx]
                 + s2 * swg[(idx + 1) & (N_ - 1)];
        float p = __powf(ws, gamma);
        wp[t] = p; lps += p;
    }
    float psum = block_reduce_sum(lps, sbuf);
    float invp = 1.f / (psum + EPSV);
    float* wout = g_w + (size_t)hd * RBN + (size_t)b * N_;
#pragma unroll
    for (int t = 0; t < 16; ++t) {
        int idx = tid + t * 256;
        wout[idx] = wp[t] * invp;
    }
}

// fin for heads 0-3 after pass A: 0,1 direct; 2,3 assembled from pass-A reductions
__global__ void finA_kernel(const float* __restrict__ prevW) {
    __shared__ float swg[N_];
    __shared__ float sbuf[8];
    int b = blockIdx.x;
    int hd = blockIdx.y;          // 0..3
    int tid = threadIdx.x;
    int hb = hd * B_ + b;
    float knorm = g_knorm[hb], beta = g_beta[hb], gate = g_gate[hb], gamma = g_gamma[hb];
    float s0 = g_s[hb * 3 + 0], s1 = g_s[hb * 3 + 1], s2 = g_s[hb * 3 + 2];
    float bk = beta / knorm;
    const float* pw = prevW + ((size_t)hd * B_ + b) * N_;
    const size_t base = (size_t)b * N_;
    float sc[16];
    if (hd < 2) {
        const float* dot = hd ? RED(1) : RED(0);
        const float* nrm = RED(2);
#pragma unroll
        for (int t = 0; t < 16; ++t) {
            int idx = tid + t * 256;
            float d = dot[base + idx];
            float nr = fmaxf(nrm[base + idx], 1e-24f);
            sc[t] = d * bk * rsqrtf(nr);
        }
    } else {
        int hh = hd - 2;
        float Ax = hh ? g_A3[b] : g_A2[b];
        float Aaa = g_Aaa[b];
        const float* ua = hh ? RED(5) : RED(3);
        const float* ub = hh ? RED(6) : RED(4);
        const float* nrm = RED(2);
        const float* r5 = RED(7); const float* r6 = RED(8);
        const float* r7 = RED(9); const float* r8 = RED(10);
        const float* wp1 = g_w + 1 * RBN + base;
#pragma unroll
        for (int t = 0; t < 16; ++t) {
            int idx = tid + t * 256;
            float w1 = wp1[idx];
            float d = ua[base + idx] + w1 * (Ax - ub[base + idx]);
            float nrm1 = nrm[base + idx]
                       + 2.f * w1 * (r5[base + idx] - r6[base + idx])
                       + w1 * w1 * (Aaa - 2.f * r7[base + idx] + r8[base + idx]);
            nrm1 = fmaxf(nrm1, 1e-24f);
            sc[t] = d * bk * rsqrtf(nrm1);
        }
    }
    fin_core(sc, hd, b, gate, s0, s1, s2, gamma, pw, sbuf, swg);
}

__global__ void fin_kernel(int head0, const float* __restrict__ prevW) {
    __shared__ float swg[N_];
    __shared__ float sbuf[8];
    int b = blockIdx.x;
    int hh = blockIdx.y;
    int hd = head0 + hh;
    int tid = threadIdx.x;
    const float* dot = hh ? RED(1) : RED(0);
    const float* nrm = RED(2);
    int hb = hd * B_ + b;
    float knorm = g_knorm[hb], beta = g_beta[hb], gate = g_gate[hb], gamma = g_gamma[hb];
    float s0 = g_s[hb * 3 + 0], s1 = g_s[hb * 3 + 1], s2 = g_s[hb * 3 + 2];
    float bk = beta / knorm;
    const float* pw = prevW + ((size_t)hd * B_ + b) * N_;
    const size_t base = (size_t)b * N_;
    float sc[16];
#pragma unroll
    for (int t = 0; t < 16; ++t) {
        int idx = tid + t * 256;
        float d = dot[base + idx];
        float nr = fmaxf(nrm[base + idx], 1e-24f);
        sc[t] = d * bk * rsqrtf(nr);
    }
    fin_core(sc, hd, b, gate, s0, s1, s2, gamma, pw, sbuf, swg);
}

// fin for head 6: assemble dot6/nrm3 from pass-D reductions + w5; also T[b] = sum w6 w5
__global__ void fin6_kernel(const float* __restrict__ prevW) {
    __shared__ float swg[N_];
    __shared__ float sbuf[8];
    int b = blockIdx.x;
    int tid = threadIdx.x;
    const int hd = 6;
    int hb = hd * B_ + b;
    float knorm = g_knorm[hb], beta = g_beta[hb], gate = g_gate[hb], gamma = g_gamma[hb];
    float s0 = g_s[hb * 3 + 0], s1 = g_s[hb * 3 + 1], s2 = g_s[hb * 3 + 2];
    float ak = g_ak[b], aa = g_aa[b];
    float bk = beta / knorm;
    const float* pw = prevW + ((size_t)hd * B_ + b) * N_;
    const float* wp5 = g_w + 5 * RBN + (size_t)b * N_;
    const size_t base = (size_t)b * N_;
    const float* d6ap = RED(0); const float* d6bp = RED(1);
    const float* q0p = RED(2);  const float* q1p = RED(3);
    const float* q2p = RED(4);  const float* p1p = RED(5);
    const float* p2p = RED(6);
    float sc[16];
#pragma unroll
    for (int t = 0; t < 16; ++t) {
        int idx = tid + t * 256;
        float w5 = wp5[idx];
        float d6 = d6ap[base + idx] + w5 * (ak - d6bp[base + idx]);
        float q0 = q0p[base + idx];
        float q1 = q1p[base + idx], q2 = q2p[base + idx];
        float p1 = p1p[base + idx], p2 = p2p[base + idx];
        float nrm3 = q0 + w5 * (-2.f * q1 + 2.f * p1) + w5 * w5 * (q2 - 2.f * p2 + aa);
        nrm3 = fmaxf(nrm3, 1e-24f);
        sc[t] = d6 * bk * rsqrtf(nrm3);
    }
    fin_core(sc, hd, b, gate, s0, s1, s2, gamma, pw, sbuf, swg);
    // T[b] = sum_n w6 w5
    const float* wout = g_w + 6 * RBN + base;
    float lt = 0.f;
#pragma unroll
    for (int t = 0; t < 16; ++t) {
        int idx = tid + t * 256;
        lt += wout[idx] * wp5[idx];
    }
    float T = block_reduce_sum(lt, sbuf);
    if (tid == 0) g_T[b] = T;
}

// ---------------- build state = [h | reads0 | reads2 | reads4 | reads6] ----------------
__global__ void build_state_kernel() {
    int b = blockIdx.x;
    for (int j = threadIdx.x; j < 768; j += blockDim.x) {
        float v;
        if (j < 512) v = g_h[(size_t)b * C_ + j];
        else {
            int ri = (j - 512) >> 6, m = (j - 512) & 63;
            if (ri < 3) {
                float s = 0.f;
                const float* rp = g_rpart + (size_t)ri * B_ * 16 * 64 + (size_t)b * 16 * 64 + m;
#pragma unroll
                for (int cc = 0; cc < 16; ++cc) s += rp[cc * 64];
                v = s;
            } else {
                float sa = 0.f, sb = 0.f;
                const float* rpa = g_rpart + (size_t)3 * B_ * 16 * 64 + (size_t)b * 16 * 64 + m;
                const float* rpb = g_rpart + (size_t)4 * B_ * 16 * 64 + (size_t)b * 16 * 64 + m;
#pragma unroll
                for (int cc = 0; cc < 16; ++cc) { sa += rpa[cc * 64]; sb += rpb[cc * 64]; }
                float e5 = g_e[((size_t)2 * B_ + b) * 64 + m];
                float a5 = g_a[((size_t)2 * B_ + b) * 64 + m];
                v = sa - e5 * sb + g_T[b] * a5;
            }
        }
        g_state[(size_t)b * 768 + j] = v;
    }
}

// ---------------- host ----------------
extern "C" void kernel_launch(void* const* d_in, const int* in_sizes, int n_in,
                              void* d_out, int out_size) {
    const float* in_data      = (const float*)d_in[0];
    const float* memory       = (const float*)d_in[1];
    const float* h0           = (const float*)d_in[2];
    const float* c0           = (const float*)d_in[3];
    const float* prev_weights = (const float*)d_in[4];
    const float* prev_reads   = (const float*)d_in[5];
    const float* W_ih         = (const float*)d_in[6];
    const float* b_ih         = (const float*)d_in[7];
    const float* W_hh         = (const float*)d_in[8];
    const float* b_hh         = (const float*)d_in[9];
    const float* W_out        = (const float*)d_in[10];
    const float* b_out        = (const float*)d_in[11];
    const float* W_addr       = (const float*)d_in[12];
    const float* b_addr       = (const float*)d_in[13];
    const float* W_ea         = (const float*)d_in[14];
    const float* b_ea         = (const float*)d_in[15];
    float* outp = (float*)d_out;

    // controller (split-K GEMMs)
    build_x_kernel<<<(B_ * 320 + 255) / 256, 256>>>(in_data, prev_reads);
    gates_gemm_kernel<<<dim3(2048 / 64, B_ / 64, 4), 256>>>(h0, W_ih, W_hh);
    lstm_kernel<<<(B_ * C_ + 255) / 256, 256>>>(c0, b_ih, b_hh);

    // head parameters (trimmed N=874: addr heads 0-6, ea heads 0-2; split-K 16)
    headpe_gemm_kernel<<<dim3((PEN + 63) / 64, B_ / 64, 16), 256>>>(W_addr, W_ea);
    head_act_kernel<<<B_, 256>>>(b_addr, b_ea);

    passA_kernel<<<NPASSBLK, 256>>>(memory);
    finA_kernel<<<dim3(B_, 4), 256>>>(prev_weights);       // heads 0-3
    passC_kernel<<<NPASSBLK, 256>>>(memory);
    fin_kernel<<<dim3(B_, 2), 256>>>(4, prev_weights);     // heads 4,5 (direct on m2)
    passD_kernel<<<NPASSBLK, 256>>>();
    fin6_kernel<<<B_, 256>>>(prev_weights);                // head 6 (assembled)
    passE_kernel<<<NPASSBLK, 256>>>();

    // output
    build_state_kernel<<<B_, 256>>>();
    out_gemm_kernel<<<dim3(1, B_ / 32, 4), 256>>>(W_out);
    out_fin_kernel<<<(B_ * 64 + 255) / 256, 256>>>(b_out, outp);
}

// round 16
// speedup vs baseline: 1.0668x; 1.0047x over previous
#include <cuda_runtime.h>
#include <cstdint>

#define B_  256
#define N_  4096
#define M_  64
#define C_  512
#define EPSV 1e-8f
#define NPASSBLK 296
#define NPBE 444
#define NPAIRS   4096
#define RBN ((size_t)B_ * N_)
#define PEN 874
#define PE1 490
#define PEB ((size_t)B_ * PEN)
#define GTB ((size_t)B_ * 2048)
#define OTB ((size_t)B_ * 64)

// ---------------- packed f32x2 helpers (sm_103a FFMA2) ----------------
struct px2 { unsigned long long u; };
__device__ __forceinline__ px2 pk(float x, float y) {
    px2 r; asm("mov.b64 %0,{%1,%2};" : "=l"(r.u) : "f"(x), "f"(y)); return r;
}
__device__ __forceinline__ float2 up(px2 a) {
    float2 f; asm("mov.b64 {%0,%1},%2;" : "=f"(f.x), "=f"(f.y) : "l"(a.u)); return f;
}
__device__ __forceinline__ px2 fma2(px2 a, px2 b, px2 c) {
    px2 r; asm("fma.rn.f32x2 %0,%1,%2,%3;" : "=l"(r.u) : "l"(a.u), "l"(b.u), "l"(c.u)); return r;
}

// ---------------- device scratch ----------------
__device__ __align__(16) float g_mem[(size_t)B_ * N_ * M_];      // v2 working memory (written once, pass C)
__device__ __align__(16) float g_x[B_ * 320];
__device__ __align__(16) float g_gates4[4 * GTB];
__device__ __align__(16) float g_c[B_ * C_];
__device__ __align__(16) float g_h[B_ * C_];
__device__ __align__(16) float g_pe8[8 * PEB];
__device__ __align__(16) float g_out4[4 * OTB];
__device__ __align__(16) float g_k[7 * B_ * M_];
__device__ float g_knorm[7 * B_];
__device__ float g_beta[7 * B_];
__device__ float g_gate[7 * B_];
__device__ float g_s[7 * B_ * 3];
__device__ float g_gamma[7 * B_];
__device__ __align__(16) float g_e[3 * B_ * M_];
__device__ __align__(16) float g_a[3 * B_ * M_];
__device__ __align__(16) float g_red[11 * RBN];                  // reduction slots
__device__ __align__(16) float g_w[7 * RBN];                     // per-head weights, slot = head index
__device__ __align__(16) float g_rpart[5 * B_ * 16 * M_];        // colsum partials: reads0,2,4, Sa, Sb
__device__ float g_ak[B_];    // a5 . k6
__device__ float g_aa[B_];    // |a5|^2
__device__ float g_A2[B_];    // a1 . k2
__device__ float g_A3[B_];    // a1 . k3
__device__ float g_Aaa[B_];   // |a1|^2
__device__ float g_T[B_];     // sum_n w6 w5
__device__ __align__(16) float g_state[B_ * 768];

#define RED(i) (g_red + (size_t)(i) * RBN)

// ---------------- helpers ----------------
__device__ __forceinline__ float sigf(float x) { return 1.f / (1.f + expf(-x)); }
__device__ __forceinline__ float softplusf(float x) { return x > 20.f ? x : log1pf(expf(x)); }

// ---------------- build x = [in_data | prev_reads 0..3] ----------------
__global__ void build_x_kernel(const float* __restrict__ in_data,
                               const float* __restrict__ prev_reads) {
    int idx = blockIdx.x * blockDim.x + threadIdx.x;
    if (idx >= B_ * 320) return;
    int b = idx / 320, j = idx % 320;
    float v;
    if (j < 64) v = in_data[b * 64 + j];
    else { int i = (j - 64) >> 6, m = (j - 64) & 63; v = prev_reads[((size_t)i * B_ + b) * 64 + m]; }
    g_x[idx] = v;
}

// gates GEMM, 64x64 tile / 4x4 microtile, split-K 4: partials -> g_gates4[z]
__global__ void gates_gemm_kernel(const float* __restrict__ h0,
                                  const float* __restrict__ Wih,
                                  const float* __restrict__ Whh) {
    __shared__ __align__(16) float As[16][64];
    __shared__ __align__(16) float Bs[16][64];
    int tid = threadIdx.x;
    int z = blockIdx.z;
    const float* A = (z < 2) ? g_x : h0;
    const float* Bw = (z < 2) ? Wih : Whh;
    int K = (z < 2) ? 320 : 512;
    int kbeg = (z == 0) ? 0 : (z == 1) ? 160 : (z == 2) ? 0 : 256;
    int kend = (z == 0) ? 160 : (z == 1) ? 320 : (z == 2) ? 256 : 512;
    int m0 = blockIdx.y * 64, n0 = blockIdx.x * 64;
    int l_r = tid >> 2, l_k = (tid & 3) * 4;
    int ty = tid >> 4, tx = tid & 15;
    float acc[4][4] = {};
    const float* ap = A + (size_t)(m0 + l_r) * K + l_k;
    const float* bp = Bw + (size_t)(n0 + l_r) * K + l_k;
    float4 av = *(const float4*)(ap + kbeg);
    float4 bv = *(const float4*)(bp + kbeg);
    for (int k0 = kbeg; k0 < kend; k0 += 16) {
        __syncthreads();
        As[l_k + 0][l_r] = av.x; As[l_k + 1][l_r] = av.y;
        As[l_k + 2][l_r] = av.z; As[l_k + 3][l_r] = av.w;
        Bs[l_k + 0][l_r] = bv.x; Bs[l_k + 1][l_r] = bv.y;
        Bs[l_k + 2][l_r] = bv.z; Bs[l_k + 3][l_r] = bv.w;
        if (k0 + 16 < kend) {
            av = *(const float4*)(ap + k0 + 16);
            bv = *(const float4*)(bp + k0 + 16);
        }
        __syncthreads();
#pragma unroll
        for (int kk = 0; kk < 16; kk++) {
            float4 a = *(const float4*)&As[kk][ty << 2];
            float4 b = *(const float4*)&Bs[kk][tx << 2];
            acc[0][0] += a.x * b.x; acc[0][1] += a.x * b.y; acc[0][2] += a.x * b.z; acc[0][3] += a.x * b.w;
            acc[1][0] += a.y * b.x; acc[1][1] += a.y * b.y; acc[1][2] += a.y * b.z; acc[1][3] += a.y * b.w;
            acc[2][0] += a.z * b.x; acc[2][1] += a.z * b.y; acc[2][2] += a.z * b.z; acc[2][3] += a.z * b.w;
            acc[3][0] += a.w * b.x; acc[3][1] += a.w * b.y; acc[3][2] += a.w * b.z; acc[3][3] += a.w * b.w;
        }
    }
    float* outp = g_gates4 + (size_t)z * GTB;
#pragma unroll
    for (int i = 0; i < 4; i++) {
        int m = m0 + (ty << 2) + i;
#pragma unroll
        for (int j = 0; j < 4; j++) {
            int n = n0 + (tx << 2) + j;
            outp[(size_t)m * 2048 + n] = acc[i][j];
        }
    }
}

// head-param GEMM, trimmed N=874, 64x64 tile / 4x4 microtile, split-K 8 x 64
__global__ void headpe_gemm_kernel(const float* __restrict__ Wa,
                                   const float* __restrict__ We) {
    __shared__ __align__(16) float As[16][64];
    __shared__ __align__(16) float Bs[16][64];
    const int K = 512;
    int tid = threadIdx.x;
    int z = blockIdx.z;
    int kbeg = z * 64, kend = kbeg + 64;
    int m0 = blockIdx.y * 64, n0 = blockIdx.x * 64;
    int l_r = tid >> 2, l_k = (tid & 3) * 4;
    int ty = tid >> 4, tx = tid & 15;
    int brow = n0 + l_r;
    const float* browp = (brow < PE1) ? (Wa + (size_t)brow * K)
                                      : (We + (size_t)(brow - PE1) * K);
    bool bok = (brow < PEN);
    const float* ap = g_c + (size_t)(m0 + l_r) * K + l_k;
    float4 av = *(const float4*)(ap + kbeg);
    float4 bv = bok ? *(const float4*)(browp + l_k + kbeg) : make_float4(0.f, 0.f, 0.f, 0.f);
    float acc[4][4] = {};
    for (int k0 = kbeg; k0 < kend; k0 += 16) {
        __syncthreads();
        As[l_k + 0][l_r] = av.x; As[l_k + 1][l_r] = av.y;
        As[l_k + 2][l_r] = av.z; As[l_k + 3][l_r] = av.w;
        Bs[l_k + 0][l_r] = bv.x; Bs[l_k + 1][l_r] = bv.y;
        Bs[l_k + 2][l_r] = bv.z; Bs[l_k + 3][l_r] = bv.w;
        if (k0 + 16 < kend) {
            av = *(const float4*)(ap + k0 + 16);
            bv = bok ? *(const float4*)(browp + l_k + k0 + 16) : make_float4(0.f, 0.f, 0.f, 0.f);
        }
        __syncthreads();
#pragma unroll
        for (int kk = 0; kk < 16; kk++) {
            float4 a = *(const float4*)&As[kk][ty << 2];
            float4 b = *(const float4*)&Bs[kk][tx << 2];
            acc[0][0] += a.x * b.x; acc[0][1] += a.x * b.y; acc[0][2] += a.x * b.z; acc[0][3] += a.x * b.w;
            acc[1][0] += a.y * b.x; acc[1][1] += a.y * b.y; acc[1][2] += a.y * b.z; acc[1][3] += a.y * b.w;
            acc[2][0] += a.z * b.x; acc[2][1] += a.z * b.y; acc[2][2] += a.z * b.z; acc[2][3] += a.z * b.w;
            acc[3][0] += a.w * b.x; acc[3][1] += a.w * b.y; acc[3][2] += a.w * b.z; acc[3][3] += a.w * b.w;
        }
    }
    float* outp = g_pe8 + (size_t)z * PEB;
#pragma unroll
    for (int i = 0; i < 4; i++) {
        int m = m0 + (ty << 2) + i;
#pragma unroll
        for (int j = 0; j < 4; j++) {
            int n = n0 + (tx << 2) + j;
            if (n < PEN) outp[(size_t)m * PEN + n] = acc[i][j];
        }
    }
}

// output GEMM, split-K 4 x 192: partials -> g_out4[z]   (N=64, K=768)
__global__ void out_gemm_kernel(const float* __restrict__ Wo) {
    __shared__ __align__(16) float As[16][32];
    __shared__ __align__(16) float Bs[16][64];
    const int NN = 64, K = 768;
    int tid = threadIdx.x;
    int z = blockIdx.z;
    int kbeg = z * 192, kend = kbeg + 192;
    int m0 = blockIdx.y * 32, n0 = 0;
    int la_r = tid >> 3, la_k = (tid & 7) * 2;
    int lb_r = tid >> 2, lb_k = (tid & 3) * 4;
    int ty = tid >> 4, tx = tid & 15;
    const float* ap = g_state + (size_t)(m0 + la_r) * K + la_k;
    const float* bp = Wo + (size_t)(n0 + lb_r) * K + lb_k;
    float2 av = *(const float2*)(ap + kbeg);
    float4 bv = *(const float4*)(bp + kbeg);
    float acc[2][4] = {};
    for (int k0 = kbeg; k0 < kend; k0 += 16) {
        __syncthreads();
        As[la_k][la_r] = av.x; As[la_k + 1][la_r] = av.y;
        Bs[lb_k + 0][lb_r] = bv.x; Bs[lb_k + 1][lb_r] = bv.y;
        Bs[lb_k + 2][lb_r] = bv.z; Bs[lb_k + 3][lb_r] = bv.w;
        if (k0 + 16 < kend) {
            av = *(const float2*)(ap + k0 + 16);
            bv = *(const float4*)(bp + k0 + 16);
        }
        __syncthreads();
#pragma unroll
        for (int kk = 0; kk < 16; kk++) {
            float2 a = *(const float2*)&As[kk][ty << 1];
            float4 b = *(const float4*)&Bs[kk][tx << 2];
            acc[0][0] += a.x * b.x; acc[0][1] += a.x * b.y; acc[0][2] += a.x * b.z; acc[0][3] += a.x * b.w;
            acc[1][0] += a.y * b.x; acc[1][1] += a.y * b.y; acc[1][2] += a.y * b.z; acc[1][3] += a.y * b.w;
        }
    }
    float* outp = g_out4 + (size_t)z * OTB;
#pragma unroll
    for (int i = 0; i < 2; i++) {
        int m = m0 + (ty << 1) + i;
#pragma unroll
        for (int j = 0; j < 4; j++) {
            int n = n0 + (tx << 2) + j;
            outp[(size_t)m * NN + n] = acc[i][j];
        }
    }
}

// out finalize: sum split-K partials + bias, sigmoid
__global__ void out_fin_kernel(const float* __restrict__ bo, float* __restrict__ C) {
    int idx = blockIdx.x * 256 + threadIdx.x;
    if (idx >= B_ * 64) return;
    int n = idx & 63;
    float s = g_out4[idx] + g_out4[OTB + idx] + g_out4[2 * OTB + idx] + g_out4[3 * OTB + idx];
    C[idx] = sigf(s + bo[n]);
}

// ---------------- LSTM pointwise (sums gates split-K partials + biases) ----------------
__global__ void lstm_kernel(const float* __restrict__ c0,
                            const float* __restrict__ bih, const float* __restrict__ bhh) {
    int idx = blockIdx.x * blockDim.x + threadIdx.x;
    if (idx >= B_ * C_) return;
    int b = idx / C_, j = idx % C_;
    size_t base = (size_t)b * 2048;
    float g4[4];
#pragma unroll
    for (int gi = 0; gi < 4; ++gi) {
        size_t o = base + gi * 512 + j;
        g4[gi] = g_gates4[o] + g_gates4[GTB + o] + g_gates4[2 * GTB + o] + g_gates4[3 * GTB + o]
               + bih[gi * 512 + j] + bhh[gi * 512 + j];
    }
    float c = sigf(g4[1]) * c0[idx] + sigf(g4[0]) * tanhf(g4[2]);
    g_c[idx] = c;
    g_h[idx] = sigf(g4[3]) * tanhf(c);
}

// ---------------- head activations (stage pe = sum 8 partials + bias into smem) ----------------
// trimmed layout: [0,490): addr heads 0..6 (70 each); [490,874): ea heads 0..2 (128 each)
__global__ void head_act_kernel(const float* __restrict__ ba, const float* __restrict__ be) {
    __shared__ float spe[PEN];
    int b = blockIdx.x;
    int tid = threadIdx.x;
    for (int j = tid; j < PEN; j += 256) {
        size_t o = (size_t)b * PEN + j;
        float bias = (j < PE1) ? ba[j] : be[j - PE1];
        float s = 0.f;
#pragma unroll
        for (int zz = 0; zz < 8; ++zz) s += g_pe8[(size_t)zz * PEB + o];
        spe[j] = s + bias;
    }
    __syncthreads();
    int wid = tid >> 5, lane = tid & 31;
    if (wid < 7) {
        int hd = wid;
        const float* p = spe + hd * 70;
        float ssq = 0.f;
        for (int j = lane; j < 64; j += 32) {
            float kv = tanhf(p[j]);
            g_k[((size_t)hd * B_ + b) * 64 + j] = kv;
            ssq += kv * kv;
        }
#pragma unroll
        for (int o = 16; o; o >>= 1) ssq += __shfl_xor_sync(0xffffffffu, ssq, o);
        if (lane == 0) {
            int hb = hd * B_ + b;
            g_knorm[hb] = sqrtf(ssq);
            g_beta[hb] = softplusf(p[64]);
            g_gate[hb] = sigf(p[65]);
            float s0 = p[66], s1 = p[67], s2 = p[68];
            float mx = fmaxf(s0, fmaxf(s1, s2));
            float e0 = expf(s0 - mx), e1 = expf(s1 - mx), e2 = expf(s2 - mx);
            float inv = 1.f / (e0 + e1 + e2);
            g_s[hb * 3 + 0] = e0 * inv; g_s[hb * 3 + 1] = e1 * inv; g_s[hb * 3 + 2] = e2 * inv;
            g_gamma[hb] = 1.f + softplusf(p[69]);
        }
    } else {
        for (int wh = 0; wh < 3; ++wh) {
            const float* ea = spe + PE1 + wh * 128;
            for (int j = lane; j < 64; j += 32) {
                g_e[((size_t)wh * B_ + b) * 64 + j] = sigf(ea[j]);
                g_a[((size_t)wh * B_ + b) * 64 + j] = tanhf(ea[64 + j]);
            }
        }
        const float* ea2 = spe + PE1 + 2 * 128;
        const float* ea0 = spe + PE1 + 0 * 128;
        const float* p6  = spe + 6 * 70;
        const float* p2  = spe + 2 * 70;
        const float* p3  = spe + 3 * 70;
        float pak = 0.f, paa = 0.f, pa2 = 0.f, pa3 = 0.f, p11 = 0.f;
        for (int j = lane; j < 64; j += 32) {
            float a5v = tanhf(ea2[64 + j]);
            float k6v = tanhf(p6[j]);
            float a1v = tanhf(ea0[64 + j]);
            float k2v = tanhf(p2[j]);
            float k3v = tanhf(p3[j]);
            pak += a5v * k6v; paa += a5v * a5v;
            pa2 += a1v * k2v; pa3 += a1v * k3v; p11 += a1v * a1v;
        }
#pragma unroll
        for (int o = 16; o; o >>= 1) {
            pak += __shfl_xor_sync(0xffffffffu, pak, o);
            paa += __shfl_xor_sync(0xffffffffu, paa, o);
            pa2 += __shfl_xor_sync(0xffffffffu, pa2, o);
            pa3 += __shfl_xor_sync(0xffffffffu, pa3, o);
            p11 += __shfl_xor_sync(0xffffffffu, p11, o);
        }
        if (lane == 0) {
            g_ak[b] = pak; g_aa[b] = paa;
            g_A2[b] = pa2; g_A3[b] = pa3; g_Aaa[b] = p11;
        }
    }
}

// =================== persistent grid-stride memory passes ===================
#define PASS_HEADB(NB)                                                      \
    int tid = threadIdx.x, lane = tid & 31, warp = tid >> 5;                \
    int c = lane & 7, rg = lane >> 3, col0 = c * 8;                         \
    int p0 = (NPAIRS * blockIdx.x) / (NB);                                  \
    int p1 = (NPAIRS * (blockIdx.x + 1)) / (NB);                            \
    int Lend = p1 * 8;
#define PASS_HEAD() PASS_HEADB(NPASSBLK)

#define LOADOP(dst, baseptr) {                                              \
    const float4* _q = (const float4*)((baseptr) + col0);                   \
    float4 _u0 = __ldg(_q), _u1 = __ldg(_q + 1);                            \
    dst[0] = pk(_u0.x, _u0.y); dst[1] = pk(_u0.z, _u0.w);                   \
    dst[2] = pk(_u1.x, _u1.y); dst[3] = pk(_u1.z, _u1.w); }
#define LOADOPN(dst, baseptr) {                                             \
    const float4* _q = (const float4*)((baseptr) + col0);                   \
    float4 _u0 = __ldg(_q), _u1 = __ldg(_q + 1);                            \
    dst[0] = pk(-_u0.x, -_u0.y); dst[1] = pk(-_u0.z, -_u0.w);               \
    dst[2] = pk(-_u1.x, -_u1.y); dst[3] = pk(-_u1.z, -_u1.w); }

__device__ __forceinline__ void reads_epilogue(px2* acc, float (*sred)[64],
                                               int lane, int warp, int c, int tid,
                                               int pair, int slot) {
    float va[8];
#pragma unroll
    for (int i = 0; i < 4; ++i) { float2 f = up(acc[i]); va[2 * i] = f.x; va[2 * i + 1] = f.y; }
#pragma unroll
    for (int t = 0; t < 8; ++t) {
        va[t] += __shfl_xor_sync(0xffffffffu, va[t], 8);
        va[t] += __shfl_xor_sync(0xffffffffu, va[t], 16);
    }
    if (lane < 8) {
#pragma unroll
        for (int t = 0; t < 8; ++t) sred[warp][c * 8 + t] = va[t];
    }
    __syncthreads();
    if (tid < 64) {
        float s = 0.f;
#pragma unroll
        for (int wv = 0; wv < 8; ++wv) s += sred[wv][tid];
        g_rpart[(size_t)slot * B_ * 16 * 64 + (size_t)pair * 64 + tid] = s;
    }
    __syncthreads();
}

// ---- Pass A: 11 reductions on mem0 (heads 0-3 material), reduce-scatter ----
// slots: 0:dot0 1:dot1 2:nrm0 3:u2a 4:u2b 5:u3a 6:u3b 7:v1a 8:v2a 9:v3a 10:v4a
__global__ __launch_bounds__(256, 2) void passA_kernel(const float* __restrict__ mem0) {
    PASS_HEAD();
    float4 bufA[4], bufB[4];
#define LD_A(L) { size_t n = (size_t)(L) * 32 + warp * 4 + rg;              \
        const float4* p = (const float4*)(mem0 + n * 64 + col0);            \
        bufA[(L) & 3] = __ldcs(p); bufB[(L) & 3] = __ldcs(p + 1); }
    LD_A(p0 * 8); LD_A(p0 * 8 + 1); LD_A(p0 * 8 + 2);
    px2 k0[4], k1[4], k2[4], k3[4], e1[4], a1[4];
    int bcur = -1;
    px2 pz = pk(0.f, 0.f);
    bool oddc = (c & 1), bit1 = (c & 2);
    int sbase = (c == 0) ? 0 : (c == 1) ? 6 : (c == 2) ? 3 : 9;
    for (int p = p0; p < p1; ++p) {
        int b = p >> 4;
        if (b != bcur) {
            bcur = b;
            LOADOP(k0, g_k + ((size_t)0 * B_ + b) * 64);
            LOADOP(k1, g_k + ((size_t)1 * B_ + b) * 64);
            LOADOP(k2, g_k + ((size_t)2 * B_ + b) * 64);
            LOADOP(k3, g_k + ((size_t)3 * B_ + b) * 64);
            LOADOP(e1, g_e + ((size_t)0 * B_ + b) * 64);
            LOADOP(a1, g_a + ((size_t)0 * B_ + b) * 64);
        }
#pragma unroll
        for (int it = 0; it < 8; ++it) {
            int L = p * 8 + it;
            if (L + 3 < Lend) LD_A(L + 3);
            size_t n = (size_t)L * 32 + warp * 4 + rg;
            float4 A = bufA[it & 3], Bv = bufB[it & 3];
            px2 v[4] = { pk(A.x, A.y), pk(A.z, A.w), pk(Bv.x, Bv.y), pk(Bv.z, Bv.w) };
            px2 d0 = pz, d1 = pz, nr = pz, u2a = pz, u2b = pz, u3a = pz, u3b = pz;
            px2 v1a = pz, v2a = pz, v3a = pz, v4a = pz;
#pragma unroll
            for (int i = 0; i < 4; ++i) {
                px2 ve = fma2(v[i], e1[i], pz);
                d0  = fma2(v[i], k0[i], d0);
                d1  = fma2(v[i], k1[i], d1);
                nr  = fma2(v[i], v[i], nr);
                u2a = fma2(v[i], k2[i], u2a);
                u3a = fma2(v[i], k3[i], u3a);
                u2b = fma2(ve, k2[i], u2b);
                u3b = fma2(ve, k3[i], u3b);
                v1a = fma2(v[i], a1[i], v1a);
                v3a = fma2(ve, a1[i], v3a);
                v2a = fma2(ve, v[i], v2a);
                v4a = fma2(ve, ve, v4a);
            }
            float s[11]; float2 f;
            f = up(d0);  s[0] = f.x + f.y;
            f = up(d1);  s[1] = f.x + f.y;
            f = up(nr);  s[2] = f.x + f.y;
            f = up(u2a); s[3] = f.x + f.y;
            f = up(u2b); s[4] = f.x + f.y;
            f = up(u3a); s[5] = f.x + f.y;
            f = up(u3b); s[6] = f.x + f.y;
            f = up(v1a); s[7] = f.x + f.y;
            f = up(v2a); s[8] = f.x + f.y;
            f = up(v3a); s[9] = f.x + f.y;
            f = up(v4a); s[10] = f.x + f.y;
            // reduce-scatter over 8 lanes (c bits)
#pragma unroll
            for (int t = 0; t < 11; ++t) s[t] += __shfl_xor_sync(0xffffffffu, s[t], 1);
            float kk[6];
            kk[0] = oddc ? s[6]  : s[0];
            kk[1] = oddc ? s[7]  : s[1];
            kk[2] = oddc ? s[8]  : s[2];
            kk[3] = oddc ? s[9]  : s[3];
            kk[4] = oddc ? s[10] : s[4];
            kk[5] = oddc ? s[10] : s[5];
#pragma unroll
            for (int t = 0; t < 6; ++t) kk[t] += __shfl_xor_sync(0xffffffffu, kk[t], 2);
            float m0v = bit1 ? kk[3] : kk[0];
            float m1v = bit1 ? kk[4] : kk[1];
            float m2v = bit1 ? kk[5] : kk[2];
            m0v += __shfl_xor_sync(0xffffffffu, m0v, 4);
            m1v += __shfl_xor_sync(0xffffffffu, m1v, 4);
            m2v += __shfl_xor_sync(0xffffffffu, m2v, 4);
            // classes: c0:{0,1,2} c1:{6,7,8} c2:{3,4,5} c3:{9,10}
            if (c < 4) {
                g_red[(size_t)sbase * RBN + n] = m0v;
                g_red[(size_t)(sbase + 1) * RBN + n] = m1v;
                if (c < 3) g_red[(size_t)(sbase + 2) * RBN + n] = m2v;
            }
        }
    }
}

// ---- Pass C: reads0 (w0,m0), m1 regs, reads2 (w2,m1), update -> write v2, dot4, dot5, nrm2 ----
// slots: 0:dot4 1:dot5 2:nrm2
__global__ __launch_bounds__(256, 2) void passC_kernel(const float* __restrict__ mem0) {
    __shared__ float sred[8][64];
    PASS_HEAD();
    const float* wp0 = g_w + 0 * RBN;
    const float* wp1 = g_w + 1 * RBN;
    const float* wp2 = g_w + 2 * RBN;
    const float* wp3 = g_w + 3 * RBN;
    float4 bufA[4], bufB[4];
#define LD_C(L) { size_t n = (size_t)(L) * 32 + warp * 4 + rg;              \
        const float4* p = (const float4*)(mem0 + n * 64 + col0);            \
        bufA[(L) & 3] = __ldcs(p); bufB[(L) & 3] = __ldcs(p + 1); }
    LD_C(p0 * 8); LD_C(p0 * 8 + 1);
    px2 k4[4], k5[4], ne1[4], a1[4], ne3[4], a3[4];
    int bcur = -1;
    px2 pz = pk(0.f, 0.f);
    for (int p = p0; p < p1; ++p) {
        int b = p >> 4;
        if (b != bcur) {
            bcur = b;
            LOADOP(k4, g_k + ((size_t)4 * B_ + b) * 64);
            LOADOP(k5, g_k + ((size_t)5 * B_ + b) * 64);
            LOADOPN(ne1, g_e + ((size_t)0 * B_ + b) * 64);
            LOADOP(a1, g_a + ((size_t)0 * B_ + b) * 64);
            LOADOPN(ne3, g_e + ((size_t)1 * B_ + b) * 64);
            LOADOP(a3, g_a + ((size_t)1 * B_ + b) * 64);
        }
        px2 acc0[4] = { pz, pz, pz, pz };
        px2 acc2[4] = { pz, pz, pz, pz };
#pragma unroll
        for (int it = 0; it < 8; ++it) {
            int L = p * 8 + it;
            if (L + 2 < Lend) LD_C(L + 2);
            size_t n = (size_t)L * 32 + warp * 4 + rg;
            float w0 = __ldg(wp0 + n), w1 = __ldg(wp1 + n);
            float w2 = __ldg(wp2 + n), w3 = __ldg(wp3 + n);
            float4 A = bufA[it & 3], Bv = bufB[it & 3];
            px2 v[4] = { pk(A.x, A.y), pk(A.z, A.w), pk(Bv.x, Bv.y), pk(Bv.z, Bv.w) };
            px2 w0p = pk(w0, w0), w1p = pk(w1, w1), w2p = pk(w2, w2), w3p = pk(w3, w3);
            px2 d4 = pz, d5 = pz, nr = pz;
#pragma unroll
            for (int i = 0; i < 4; ++i) {
                acc0[i] = fma2(w0p, v[i], acc0[i]);              // reads0 on m0
                px2 t = fma2(ne1[i], v[i], a1[i]);
                px2 m1 = fma2(w1p, t, v[i]);
                acc2[i] = fma2(w2p, m1, acc2[i]);                // reads2 on m1
                px2 t3 = fma2(ne3[i], m1, a3[i]);
                px2 m2 = fma2(w3p, t3, m1);
                v[i] = m2;
                d4 = fma2(m2, k4[i], d4);
                d5 = fma2(m2, k5[i], d5);
                nr = fma2(m2, m2, nr);
            }
            float* po = g_mem + n * 64 + col0;
            float2 f0 = up(v[0]), f1 = up(v[1]);
            __stcs((float4*)po, make_float4(f0.x, f0.y, f1.x, f1.y));
            float2 f2 = up(v[2]), f3 = up(v[3]);
            __stcs((float4*)po + 1, make_float4(f2.x, f2.y, f3.x, f3.y));
            float2 fd4 = up(d4), fd5 = up(d5), fn = up(nr);
            float s0 = fd4.x + fd4.y, s1 = fd5.x + fd5.y, sn = fn.x + fn.y;
#pragma unroll
            for (int o = 1; o <= 4; o <<= 1) {
                s0 += __shfl_xor_sync(0xffffffffu, s0, o);
                s1 += __shfl_xor_sync(0xffffffffu, s1, o);
                sn += __shfl_xor_sync(0xffffffffu, sn, o);
            }
            // lane-distributed store: lane c stores slot c (c<3)
            float outv = (c == 0) ? s0 : (c == 1) ? s1 : sn;
            if (c < 3) g_red[(size_t)c * RBN + n] = outv;
        }
        reads_epilogue(acc0, sred, lane, warp, c, tid, p, 0);
        reads_epilogue(acc2, sred, lane, warp, c, tid, p, 1);
    }
}

// ---- Pass D: reads4 + algebraic reductions for head 6 on v2 (NO memory write) ----
// values: 0:d6a 1:d6b 2:q1 3:q2 4:p1 5:p2 -> slots {0,1,3,4,5,6} (slot2 = nrm2 preserved)
__global__ __launch_bounds__(256, 2) void passD_kernel() {
    __shared__ float sred[8][64];
    PASS_HEAD();
    const float* wp4 = g_w + 4 * RBN;
    float4 bufA[4], bufB[4];
#define LD_D(L) { size_t n = (size_t)(L) * 32 + warp * 4 + rg;              \
        const float4* p = (const float4*)(g_mem + n * 64 + col0);           \
        bufA[(L) & 3] = __ldcs(p); bufB[(L) & 3] = __ldcs(p + 1); }
    LD_D(p0 * 8); LD_D(p0 * 8 + 1); LD_D(p0 * 8 + 2);
    px2 k6[4], ek[4], e5[4], es[4], a5[4], ea[4];
    int bcur = -1;
    px2 pz = pk(0.f, 0.f);
    bool oddc = (c & 1), bit1 = (c & 2);
    // classes: c0:{v0,v1}->slots{0,1}; c1:{v3,v4}->slots{4,5}; c2:{v2}->slot{3}; c3:{v5}->slot{6}
    int slotA = (c == 0) ? 0 : (c == 1) ? 4 : (c == 2) ? 3 : 6;
    int slotB = (c == 0) ? 1 : 5;
    for (int p = p0; p < p1; ++p) {
        int b = p >> 4;
        if (b != bcur) {
            bcur = b;
            float kk[8], ee[8], av[8];
            const float4* qk = (const float4*)(g_k + ((size_t)6 * B_ + b) * 64 + col0);
            const float4* qe = (const float4*)(g_e + ((size_t)2 * B_ + b) * 64 + col0);
            const float4* qa = (const float4*)(g_a + ((size_t)2 * B_ + b) * 64 + col0);
            *(float4*)&kk[0] = __ldg(qk); *(float4*)&kk[4] = __ldg(qk + 1);
            *(float4*)&ee[0] = __ldg(qe); *(float4*)&ee[4] = __ldg(qe + 1);
            *(float4*)&av[0] = __ldg(qa); *(float4*)&av[4] = __ldg(qa + 1);
#pragma unroll
            for (int i = 0; i < 4; ++i) {
                float k0v = kk[2*i], k1v = kk[2*i+1];
                float e0v = ee[2*i], e1v = ee[2*i+1];
                float a0v = av[2*i], a1v = av[2*i+1];
                k6[i] = pk(k0v, k1v);
                e5[i] = pk(e0v, e1v);
                ek[i] = pk(e0v * k0v, e1v * k1v);
                es[i] = pk(e0v * e0v, e1v * e1v);
                a5[i] = pk(a0v, a1v);
                ea[i] = pk(e0v * a0v, e1v * a1v);
            }
        }
        px2 acc[4] = { pz, pz, pz, pz };
#pragma unroll
        for (int it = 0; it < 8; ++it) {
            int L = p * 8 + it;
            if (L + 3 < Lend) LD_D(L + 3);
            size_t n = (size_t)L * 32 + warp * 4 + rg;
            float w4 = __ldg(wp4 + n);
            float4 A = bufA[it & 3], Bv = bufB[it & 3];
            px2 v[4] = { pk(A.x, A.y), pk(A.z, A.w), pk(Bv.x, Bv.y), pk(Bv.z, Bv.w) };
            px2 w4p = pk(w4, w4);
            px2 d6a = pz, d6b = pz, q1 = pz, q2 = pz, p1v = pz, p2v = pz;
#pragma unroll
            for (int i = 0; i < 4; ++i) {
                acc[i] = fma2(w4p, v[i], acc[i]);               // reads4 on m2
                px2 vsq = fma2(v[i], v[i], pz);
                d6a = fma2(v[i], k6[i], d6a);
                d6b = fma2(v[i], ek[i], d6b);
                q1  = fma2(vsq, e5[i], q1);
                q2  = fma2(vsq, es[i], q2);
                p1v = fma2(v[i], a5[i], p1v);
                p2v = fma2(v[i], ea[i], p2v);
            }
            float s[6]; float2 f;
            f = up(d6a); s[0] = f.x + f.y;
            f = up(d6b); s[1] = f.x + f.y;
            f = up(q1);  s[2] = f.x + f.y;
            f = up(q2);  s[3] = f.x + f.y;
            f = up(p1v); s[4] = f.x + f.y;
            f = up(p2v); s[5] = f.x + f.y;
#pragma unroll
            for (int t = 0; t < 6; ++t) s[t] += __shfl_xor_sync(0xffffffffu, s[t], 1);
            float kk0 = oddc ? s[3] : s[0];
            float kk1 = oddc ? s[4] : s[1];
            float kk2 = oddc ? s[5] : s[2];
            kk0 += __shfl_xor_sync(0xffffffffu, kk0, 2);
            kk1 += __shfl_xor_sync(0xffffffffu, kk1, 2);
            kk2 += __shfl_xor_sync(0xffffffffu, kk2, 2);
            float m0v = bit1 ? kk2 : kk0;
            float m1v = bit1 ? kk2 : kk1;   // m1v only valid for c<2 classes
            m0v += __shfl_xor_sync(0xffffffffu, m0v, 4);
            m1v += __shfl_xor_sync(0xffffffffu, m1v, 4);
            if (c < 4) g_red[(size_t)slotA * RBN + n] = m0v;
            if (c < 2) g_red[(size_t)slotB * RBN + n] = m1v;
        }
        reads_epilogue(acc, sred, lane, warp, c, tid, p, 2);
    }
}

// ---- Pass E: Sa = colsum(w6, v2), Sb = colsum(w6*w5, v2) ----
__global__ __launch_bounds__(256, 3) void passE_kernel() {
    __shared__ float sredA[8][64];
    __shared__ float sredB[8][64];
    PASS_HEADB(NPBE);
    const float* wp5 = g_w + 5 * RBN;
    const float* wp6 = g_w + 6 * RBN;
    float4 bufA[4], bufB[4];
#define LD_E(L) { size_t n = (size_t)(L) * 32 + warp * 4 + rg;              \
        const float4* p = (const float4*)(g_mem + n * 64 + col0);           \
        bufA[(L) & 3] = __ldcs(p); bufB[(L) & 3] = __ldcs(p + 1); }
    LD_E(p0 * 8); LD_E(p0 * 8 + 1); LD_E(p0 * 8 + 2);
    for (int p = p0; p < p1; ++p) {
        px2 accA[4], accB[4];
#pragma unroll
        for (int i = 0; i < 4; ++i) { accA[i] = pk(0.f, 0.f); accB[i] = pk(0.f, 0.f); }
#pragma unroll
        for (int it = 0; it < 8; ++it) {
            int L = p * 8 + it;
            if (L + 3 < Lend) LD_E(L + 3);
            size_t n = (size_t)L * 32 + warp * 4 + rg;
            float w5 = __ldg(wp5 + n), w6 = __ldg(wp6 + n);
            float4 A = bufA[it & 3], Bv = bufB[it & 3];
            px2 v[4] = { pk(A.x, A.y), pk(A.z, A.w), pk(Bv.x, Bv.y), pk(Bv.z, Bv.w) };
            px2 w6p = pk(w6, w6), w65p = pk(w6 * w5, w6 * w5);
#pragma unroll
            for (int i = 0; i < 4; ++i) {
                accA[i] = fma2(w6p, v[i], accA[i]);
                accB[i] = fma2(w65p, v[i], accB[i]);
            }
        }
        reads_epilogue(accA, sredA, lane, warp, c, tid, p, 3);
        reads_epilogue(accB, sredB, lane, warp, c, tid, p, 4);
    }
}

// ---------------- finalize helpers ----------------
__device__ __forceinline__ float block_reduce_max(float v, float* sbuf) {
#pragma unroll
    for (int o = 16; o; o >>= 1) v = fmaxf(v, __shfl_xor_sync(0xffffffffu, v, o));
    int lane = threadIdx.x & 31, w = threadIdx.x >> 5;
    if (lane == 0) sbuf[w] = v;
    __syncthreads();
    if (threadIdx.x < 32) {
        float vv = (threadIdx.x < 8) ? sbuf[threadIdx.x] : -3.4e38f;
#pragma unroll
        for (int o = 4; o; o >>= 1) vv = fmaxf(vv, __shfl_xor_sync(0xffffffffu, vv, o));
        if (threadIdx.x == 0) sbuf[0] = vv;
    }
    __syncthreads();
    v = sbuf[0];
    __syncthreads();
    return v;
}
__device__ __forceinline__ float block_reduce_sum(float v, float* sbuf) {
#pragma unroll
    for (int o = 16; o; o >>= 1) v += __shfl_xor_sync(0xffffffffu, v, o);
    int lane = threadIdx.x & 31, w = threadIdx.x >> 5;
    if (lane == 0) sbuf[w] = v;
    __syncthreads();
    if (threadIdx.x < 32) {
        float vv = (threadIdx.x < 8) ? sbuf[threadIdx.x] : 0.f;
#pragma unroll
        for (int o = 4; o; o >>= 1) vv += __shfl_xor_sync(0xffffffffu, vv, o);
        if (threadIdx.x == 0) sbuf[0] = vv;
    }
    __syncthreads();
    v = sbuf[0];
    __syncthreads();
    return v;
}

// softmax/interp/shift/sharpen from per-element score sc[] -> w_hd
__device__ __forceinline__ void fin_core(float* sc, int hd, int b, float gate,
                                         float s0, float s1, float s2, float gamma,
                                         const float* pw, float* sbuf, float* swg) {
    int tid = threadIdx.x;
    float lmax = -3.4e38f;
#pragma unroll
    for (int t = 0; t < 16; ++t) lmax = fmaxf(lmax, sc[t]);
    float bmax = block_reduce_max(lmax, sbuf);
    float lsum = 0.f;
#pragma unroll
    for (int t = 0; t < 16; ++t) { float e = __expf(sc[t] - bmax); sc[t] = e; lsum += e; }
    float bsum = block_reduce_sum(lsum, sbuf);
    float inv = 1.f / bsum;
#pragma unroll
    for (int t = 0; t < 16; ++t) {
        int idx = tid + t * 256;
        swg[idx] = gate * sc[t] * inv + (1.f - gate) * pw[idx];
    }
    __syncthreads();
    float wp[16];
    float lps = 0.f;
#pragma unroll
    for (int t = 0; t < 16; ++t) {
        int idx = tid + t * 256;
        float ws = s0 * swg[(idx + N_ - 1) & (N_ - 1)] + s1 * swg[idx]
                 + s2 * swg[(idx + 1) & (N_ - 1)];
        float p = __powf(ws, gamma);
        wp[t] = p; lps += p;
    }
    float psum = block_reduce_sum(lps, sbuf);
    float invp = 1.f / (psum + EPSV);
    float* wout = g_w + (size_t)hd * RBN + (size_t)b * N_;
#pragma unroll
    for (int t = 0; t < 16; ++t) {
        int idx = tid + t * 256;
        wout[idx] = wp[t] * invp;
    }
}

// fin for heads 0-3 after pass A: 0,1 direct; 2,3 assembled from pass-A reductions
__global__ void finA_kernel(const float* __restrict__ prevW) {
    __shared__ float swg[N_];
    __shared__ float sbuf[8];
    int b = blockIdx.x;
    int hd = blockIdx.y;          // 0..3
    int tid = threadIdx.x;
    int hb = hd * B_ + b;
    float knorm = g_knorm[hb], beta = g_beta[hb], gate = g_gate[hb], gamma = g_gamma[hb];
    float s0 = g_s[hb * 3 + 0], s1 = g_s[hb * 3 + 1], s2 = g_s[hb * 3 + 2];
    float bk = beta / knorm;
    const float* pw = prevW + ((size_t)hd * B_ + b) * N_;
    const size_t base = (size_t)b * N_;
    float sc[16];
    if (hd < 2) {
        const float* dot = hd ? RED(1) : RED(0);
        const float* nrm = RED(2);
#pragma unroll
        for (int t = 0; t < 16; ++t) {
            int idx = tid + t * 256;
            float d = dot[base + idx];
            float nr = fmaxf(nrm[base + idx], 1e-24f);
            sc[t] = d * bk * rsqrtf(nr);
        }
    } else {
        int hh = hd - 2;
        float Ax = hh ? g_A3[b] : g_A2[b];
        float Aaa = g_Aaa[b];
        const float* ua = hh ? RED(5) : RED(3);
        const float* ub = hh ? RED(6) : RED(4);
        const float* nrm = RED(2);
        const float* r5 = RED(7); const float* r6 = RED(8);
        const float* r7 = RED(9); const float* r8 = RED(10);
        const float* wp1 = g_w + 1 * RBN + base;
#pragma unroll
        for (int t = 0; t < 16; ++t) {
            int idx = tid + t * 256;
            float w1 = wp1[idx];
            float d = ua[base + idx] + w1 * (Ax - ub[base + idx]);
            float nrm1 = nrm[base + idx]
                       + 2.f * w1 * (r5[base + idx] - r6[base + idx])
                       + w1 * w1 * (Aaa - 2.f * r7[base + idx] + r8[base + idx]);
            nrm1 = fmaxf(nrm1, 1e-24f);
            sc[t] = d * bk * rsqrtf(nrm1);
        }
    }
    fin_core(sc, hd, b, gate, s0, s1, s2, gamma, pw, sbuf, swg);
}

__global__ void fin_kernel(int head0, const float* __restrict__ prevW) {
    __shared__ float swg[N_];
    __shared__ float sbuf[8];
    int b = blockIdx.x;
    int hh = blockIdx.y;
    int hd = head0 + hh;
    int tid = threadIdx.x;
    const float* dot = hh ? RED(1) : RED(0);
    const float* nrm = RED(2);
    int hb = hd * B_ + b;
    float knorm = g_knorm[hb], beta = g_beta[hb], gate = g_gate[hb], gamma = g_gamma[hb];
    float s0 = g_s[hb * 3 + 0], s1 = g_s[hb * 3 + 1], s2 = g_s[hb * 3 + 2];
    float bk = beta / knorm;
    const float* pw = prevW + ((size_t)hd * B_ + b) * N_;
    const size_t base = (size_t)b * N_;
    float sc[16];
#pragma unroll
    for (int t = 0; t < 16; ++t) {
        int idx = tid + t * 256;
        float d = dot[base + idx];
        float nr = fmaxf(nrm[base + idx], 1e-24f);
        sc[t] = d * bk * rsqrtf(nr);
    }
    fin_core(sc, hd, b, gate, s0, s1, s2, gamma, pw, sbuf, swg);
}

// fin for head 6: assemble dot6/nrm3 from pass-D reductions + w5; also T[b] = sum w6 w5
__global__ void fin6_kernel(const float* __restrict__ prevW) {
    __shared__ float swg[N_];
    __shared__ float sbuf[8];
    int b = blockIdx.x;
    int tid = threadIdx.x;
    const int hd = 6;
    int hb = hd * B_ + b;
    float knorm = g_knorm[hb], beta = g_beta[hb], gate = g_gate[hb], gamma = g_gamma[hb];
    float s0 = g_s[hb * 3 + 0], s1 = g_s[hb * 3 + 1], s2 = g_s[hb * 3 + 2];
    float ak = g_ak[b], aa = g_aa[b];
    float bk = beta / knorm;
    const float* pw = prevW + ((size_t)hd * B_ + b) * N_;
    const float* wp5 = g_w + 5 * RBN + (size_t)b * N_;
    const size_t base = (size_t)b * N_;
    const float* d6ap = RED(0); const float* d6bp = RED(1);
    const float* q0p = RED(2);  const float* q1p = RED(3);
    const float* q2p = RED(4);  const float* p1p = RED(5);
    const float* p2p = RED(6);
    float sc[16];
#pragma unroll
    for (int t = 0; t < 16; ++t) {
        int idx = tid + t * 256;
        float w5 = wp5[idx];
        float d6 = d6ap[base + idx] + w5 * (ak - d6bp[base + idx]);
        float q0 = q0p[base + idx];
        float q1 = q1p[base + idx], q2 = q2p[base + idx];
        float p1 = p1p[base + idx], p2 = p2p[base + idx];
        float nrm3 = q0 + w5 * (-2.f * q1 + 2.f * p1) + w5 * w5 * (q2 - 2.f * p2 + aa);
        nrm3 = fmaxf(nrm3, 1e-24f);
        sc[t] = d6 * bk * rsqrtf(nrm3);
    }
    fin_core(sc, hd, b, gate, s0, s1, s2, gamma, pw, sbuf, swg);
    // T[b] = sum_n w6 w5
    const float* wout = g_w + 6 * RBN + base;
    float lt = 0.f;
#pragma unroll
    for (int t = 0; t < 16; ++t) {
        int idx = tid + t * 256;
        lt += wout[idx] * wp5[idx];
    }
    float T = block_reduce_sum(lt, sbuf);
    if (tid == 0) g_T[b] = T;
}

// ---------------- build state = [h | reads0 | reads2 | reads4 | reads6] ----------------
__global__ void build_state_kernel() {
    int b = blockIdx.x;
    for (int j = threadIdx.x; j < 768; j += blockDim.x) {
        float v;
        if (j < 512) v = g_h[(size_t)b * C_ + j];
        else {
            int ri = (j - 512) >> 6, m = (j - 512) & 63;
            if (ri < 3) {
                float s = 0.f;
                const float* rp = g_rpart + (size_t)ri * B_ * 16 * 64 + (size_t)b * 16 * 64 + m;
#pragma unroll
                for (int cc = 0; cc < 16; ++cc) s += rp[cc * 64];
                v = s;
            } else {
                float sa = 0.f, sb = 0.f;
                const float* rpa = g_rpart + (size_t)3 * B_ * 16 * 64 + (size_t)b * 16 * 64 + m;
                const float* rpb = g_rpart + (size_t)4 * B_ * 16 * 64 + (size_t)b * 16 * 64 + m;
#pragma unroll
                for (int cc = 0; cc < 16; ++cc) { sa += rpa[cc * 64]; sb += rpb[cc * 64]; }
                float e5 = g_e[((size_t)2 * B_ + b) * 64 + m];
                float a5 = g_a[((size_t)2 * B_ + b) * 64 + m];
                v = sa - e5 * sb + g_T[b] * a5;
            }
        }
        g_state[(size_t)b * 768 + j] = v;
    }
}

// ---------------- host ----------------
extern "C" void kernel_launch(void* const* d_in, const int* in_sizes, int n_in,
                              void* d_out, int out_size) {
    const float* in_data      = (const float*)d_in[0];
    const float* memory       = (const float*)d_in[1];
    const float* h0           = (const float*)d_in[2];
    const float* c0           = (const float*)d_in[3];
    const float* prev_weights = (const float*)d_in[4];
    const float* prev_reads   = (const float*)d_in[5];
    const float* W_ih         = (const float*)d_in[6];
    const float* b_ih         = (const float*)d_in[7];
    const float* W_hh         = (const float*)d_in[8];
    const float* b_hh         = (const float*)d_in[9];
    const float* W_out        = (const float*)d_in[10];
    const float* b_out        = (const float*)d_in[11];
    const float* W_addr       = (const float*)d_in[12];
    const float* b_addr       = (const float*)d_in[13];
    const float* W_ea         = (const float*)d_in[14];
    const float* b_ea         = (const float*)d_in[15];
    float* outp = (float*)d_out;

    // controller (split-K GEMMs)
    build_x_kernel<<<(B_ * 320 + 255) / 256, 256>>>(in_data, prev_reads);
    gates_gemm_kernel<<<dim3(2048 / 64, B_ / 64, 4), 256>>>(h0, W_ih, W_hh);
    lstm_kernel<<<(B_ * C_ + 255) / 256, 256>>>(c0, b_ih, b_hh);

    // head parameters (trimmed N=874: addr heads 0-6, ea heads 0-2; split-K 8)
    headpe_gemm_kernel<<<dim3((PEN + 63) / 64, B_ / 64, 8), 256>>>(W_addr, W_ea);
    head_act_kernel<<<B_, 256>>>(b_addr, b_ea);

    passA_kernel<<<NPASSBLK, 256>>>(memory);
    finA_kernel<<<dim3(B_, 4), 256>>>(prev_weights);       // heads 0-3
    passC_kernel<<<NPASSBLK, 256>>>(memory);
    fin_kernel<<<dim3(B_, 2), 256>>>(4, prev_weights);     // heads 4,5 (direct on m2)
    passD_kernel<<<NPASSBLK, 256>>>();
    fin6_kernel<<<B_, 256>>>(prev_weights);                // head 6 (assembled)
    passE_kernel<<<NPBE, 256>>>();

    // output
    build_state_kernel<<<B_, 256>>>();
    out_gemm_kernel<<<dim3(1, B_ / 32, 4), 256>>>(W_out);
    out_fin_kernel<<<(B_ * 64 + 255) / 256, 256>>>(b_out, outp);
}